// round 5
// baseline (speedup 1.0000x reference)
#include <cuda_runtime.h>
#include <cstdint>
#include <math.h>

#define Bsz 1024
#define Dd  512
#define Nn  16
#define Hh  512
#define M_TOT 16384
#define KA   1024                // A row bytes: [Ah(512) | Al(512)]
#define KB   1536                // B row bytes: [Bh | Bl | Bh]
#define KS   128                 // int8 K per pipeline stage
#define NCH  12                  // 4 (AhBh) + 8 (AhBl, AlBh)
#define TM   128
#define TN   128
#define ROWB 144                 // smem row stride (128B data + 16B pad)
#define STG_A (TM * ROWB)
#define STG_B (TN * ROWB)
#define STG   (STG_A + STG_B)    // 36864
#define NSTAGE 3
#define SMEM_TOTAL (NSTAGE * STG)   // 110592

// ---------------- scratch ----------------
__device__ uint8_t g_Aq0[(size_t)M_TOT * KA];
__device__ uint8_t g_Aq1[(size_t)M_TOT * KA];
__device__ uint8_t g_W1q[(size_t)Dd * KB];
__device__ uint8_t g_W2q[(size_t)Dd * KB];
__device__ uint8_t g_Wcq[(size_t)Nn * Hh * KB];
__device__ float   g_F[(size_t)M_TOT * Dd];       // fp32 activations
__device__ float   g_part[4 * (size_t)M_TOT * Nn];
__device__ float   g_scl[8];   // 0:x 1:Ws1 2:Ws2 3:Wc1 4:h 5:shared

// ---------------- helpers ----------------
static __device__ __forceinline__ uint32_t smem_u32(const void* p) {
    uint32_t a;
    asm("{ .reg .u64 t; cvta.to.shared.u64 t, %1; cvt.u32.u64 %0, t; }" : "=r"(a) : "l"(p));
    return a;
}
static __device__ __forceinline__ float lrelu(float v) { return v >= 0.0f ? v : 0.1f * v; }
static __device__ __forceinline__ void q15(float q, int8_t& hi, int8_t& lo) {
    int h = __float2int_rn(q);
    h = max(-127, min(127, h));
    int l = __float2int_rn((q - (float)h) * 128.0f);
    l = max(-127, min(127, l));
    hi = (int8_t)h; lo = (int8_t)l;
}
static __device__ __forceinline__ void amax_atomic(float v, float* dst) {
    atomicMax(reinterpret_cast<int*>(dst), __float_as_int(v)); // v >= 0
}

#define LDSM4(r, a)                                                                     \
    asm volatile("ldmatrix.sync.aligned.m8n8.x4.shared.b16 {%0,%1,%2,%3}, [%4];"        \
                 : "=r"((r)[0]), "=r"((r)[1]), "=r"((r)[2]), "=r"((r)[3]) : "r"(a))
#define IMMA(d, a, b0, b1)                                                              \
    asm volatile("mma.sync.aligned.m16n8k32.row.col.s32.s8.s8.s32 "                     \
                 "{%0,%1,%2,%3},{%4,%5,%6,%7},{%8,%9},{%0,%1,%2,%3};"                   \
                 : "+r"((d)[0]), "+r"((d)[1]), "+r"((d)[2]), "+r"((d)[3])               \
                 : "r"((a)[0]), "r"((a)[1]), "r"((a)[2]), "r"((a)[3]), "r"(b0), "r"(b1))
#define CPA(dst, src) asm volatile("cp.async.cg.shared.global [%0], [%1], 16;" :: "r"(dst), "l"(src))
#define CPC()  asm volatile("cp.async.commit_group;" ::: "memory")
#define CPW1() asm volatile("cp.async.wait_group 1;" ::: "memory")
#define CPW0() asm volatile("cp.async.wait_group 0;" ::: "memory")

// ---------------------------------------------------------------------------
__global__ void k_clear() { if (threadIdx.x < 8) g_scl[threadIdx.x] = 0.0f; }

__global__ void k_absmax(const float* __restrict__ p, int n4, int idx) {
    const float4* p4 = reinterpret_cast<const float4*>(p);
    float m = 0.0f;
    for (int i = blockIdx.x * blockDim.x + threadIdx.x; i < n4; i += gridDim.x * blockDim.x) {
        float4 q = p4[i];
        m = fmaxf(m, fmaxf(fmaxf(fabsf(q.x), fabsf(q.y)), fmaxf(fabsf(q.z), fabsf(q.w))));
    }
#pragma unroll
    for (int s = 16; s > 0; s >>= 1) m = fmaxf(m, __shfl_xor_sync(0xffffffffu, m, s));
    __shared__ float red[8];
    if ((threadIdx.x & 31) == 0) red[threadIdx.x >> 5] = m;
    __syncthreads();
    if (threadIdx.x == 0) {
        float t = red[0];
#pragma unroll
        for (int w = 1; w < 8; w++) t = fmaxf(t, red[w]);
        amax_atomic(t, &g_scl[idx]);
    }
}

// ---------------------------------------------------------------------------
// quantize x (B, D, N) fp32 -> g_Aq0[m = n*B + b] rows [Ah|Al]
// ---------------------------------------------------------------------------
__global__ void k_quant_x(const float* __restrict__ x) {
    __shared__ float sm[Dd * 17];
    int b = blockIdx.x;
    const float4* xp = reinterpret_cast<const float4*>(x + (size_t)b * Dd * Nn);
    for (int v = threadIdx.x; v < 2048; v += blockDim.x) {
        float4 q = xp[v];
        int d = v >> 2, n0 = (v & 3) * 4;
        sm[d * 17 + n0 + 0] = q.x; sm[d * 17 + n0 + 1] = q.y;
        sm[d * 17 + n0 + 2] = q.z; sm[d * 17 + n0 + 3] = q.w;
    }
    __syncthreads();
    float inv = 127.0f / g_scl[0];
    int d0 = (threadIdx.x & 127) * 4;
    int nh = threadIdx.x >> 7;                  // 0 or 1
    for (int nb = 0; nb < Nn; nb += 2) {
        int n = nb + nh;
        uint8_t* row = g_Aq0 + (size_t)(n * Bsz + b) * KA;
        int8_t h[4], l[4];
#pragma unroll
        for (int e = 0; e < 4; e++) q15(sm[(d0 + e) * 17 + n] * inv, h[e], l[e]);
        *reinterpret_cast<uchar4*>(row + d0)       = make_uchar4(h[0], h[1], h[2], h[3]);
        *reinterpret_cast<uchar4*>(row + 512 + d0) = make_uchar4(l[0], l[1], l[2], l[3]);
    }
}

// ---------------------------------------------------------------------------
// quantize + transpose weights W[k][j] -> rows [j]: [Bh | Bl | Bh]
// z = 0: Ws1 ; z = 1: Ws2 ; z >= 2: Wc1[n = z-2]
// ---------------------------------------------------------------------------
__global__ void k_quant_w(const float* __restrict__ Ws1,
                          const float* __restrict__ Ws2,
                          const float* __restrict__ Wc1) {
    __shared__ float sm[32][33];
    int z = blockIdx.z;
    const float* in;
    uint8_t* out;
    float inv;
    if (z == 0)      { in = Ws1; out = g_W1q; inv = 127.0f / g_scl[1]; }
    else if (z == 1) { in = Ws2; out = g_W2q; inv = 127.0f / g_scl[2]; }
    else             { in = Wc1 + (size_t)(z - 2) * Dd * Hh;
                       out = g_Wcq + (size_t)(z - 2) * Hh * KB; inv = 127.0f / g_scl[3]; }
    int k0 = blockIdx.x * 32, j0 = blockIdx.y * 32;
    int tx = threadIdx.x, ty = threadIdx.y;
#pragma unroll
    for (int i = 0; i < 4; i++) {
        int r = ty + i * 8;
        sm[r][tx] = in[(size_t)(k0 + r) * Dd + j0 + tx];
    }
    __syncthreads();
#pragma unroll
    for (int i = 0; i < 4; i++) {
        int r = ty + i * 8;                 // local j
        int8_t h, l;
        q15(sm[tx][r] * inv, h, l);
        uint8_t* row = out + (size_t)(j0 + r) * KB;
        row[k0 + tx] = (uint8_t)h;
        row[512 + k0 + tx] = (uint8_t)l;
        row[1024 + k0 + tx] = (uint8_t)h;
    }
}

// ---------------------------------------------------------------------------
// quantize fp32 activations -> [Ah|Al] rows
// ---------------------------------------------------------------------------
__global__ void k_quant_a(int sidx, uint8_t* __restrict__ out) {
    float inv = 127.0f / g_scl[sidx];
    int i4 = blockIdx.x * blockDim.x + threadIdx.x;   // float4 index, 2.1M total
    if (i4 >= M_TOT * Dd / 4) return;
    int idx = i4 * 4, m = idx >> 9, k = idx & 511;
    float4 q = *reinterpret_cast<const float4*>(g_F + idx);
    int8_t h[4], l[4];
    q15(q.x * inv, h[0], l[0]); q15(q.y * inv, h[1], l[1]);
    q15(q.z * inv, h[2], l[2]); q15(q.w * inv, h[3], l[3]);
    uint8_t* row = out + (size_t)m * KA;
    *reinterpret_cast<uchar4*>(row + k)       = make_uchar4(h[0], h[1], h[2], h[3]);
    *reinterpret_cast<uchar4*>(row + 512 + k) = make_uchar4(l[0], l[1], l[2], l[3]);
}

// ---------------------------------------------------------------------------
// IMMA GEMM: CTA 128x128, warp 64x32, 12 chunks of k128 int8, 3-stage cp.async.
// acc = 128*sum(AhBh) + sum(AhBl) + sum(AlBh);  value = acc * sA*sB/(127*127*128)
// MODE 0/1: g_F = lrelu(val + bias); track absmax -> g_scl[oidx]
// MODE 2:   g_part[jt][m][n] = sum_h lrelu(val + bc1) * Wc2
// ---------------------------------------------------------------------------
template <int MODE>
__global__ void __launch_bounds__(256, 2)
k_imma(const uint8_t* __restrict__ Ag,
       const uint8_t* __restrict__ Bg,
       const float* __restrict__ bias,
       const float* __restrict__ wc2,
       int aidx, int bidx, int oidx) {
    extern __shared__ char smem[];
    uint32_t sb = smem_u32(smem);
    int tid = threadIdx.x, lane = tid & 31, wid = tid >> 5;
    int wm = wid & 1, wn = wid >> 1;

    int jt = blockIdx.x;
    int n  = (MODE == 2) ? blockIdx.y : 0;
    int m0 = ((MODE == 2) ? blockIdx.z : blockIdx.y) * TM;
    int j0 = jt * TN;

    const uint8_t* Ap = Ag + (size_t)m0 * KA;
    const uint8_t* Bp = Bg + ((size_t)n * Hh + j0) * KB;

    int acc[4][4][4];
#pragma unroll
    for (int a = 0; a < 4; a++)
#pragma unroll
        for (int b = 0; b < 4; b++)
#pragma unroll
            for (int c = 0; c < 4; c++) acc[a][b][c] = 0;

    uint32_t a_off[4], b_off[2];
#pragma unroll
    for (int mi = 0; mi < 4; mi++)
        a_off[mi] = (uint32_t)((wm * 64 + mi * 16 + (lane & 15)) * ROWB + (lane >> 4) * 16);
#pragma unroll
    for (int p = 0; p < 2; p++)
        b_off[p] = (uint32_t)(STG_A + (wn * 32 + p * 16 + (lane & 15)) * ROWB + (lane >> 4) * 16);

    // chunk c: A byte offset = (c<4 ? c : c-4)*128 ; B byte offset = c*128
#define AOFF(c) (((c) < 4 ? (c) : (c) - 4) * 128)

    // ---- prologue: stages 0, 1 ----
#pragma unroll
    for (int s = 0; s < 2; s++) {
        uint32_t base = sb + s * STG;
#pragma unroll
        for (int i = 0; i < 4; i++) {
            int idx = tid + i * 256, row = idx >> 3, seg = idx & 7;
            CPA(base + row * ROWB + seg * 16, Ap + (size_t)row * KA + AOFF(s) + seg * 16);
        }
#pragma unroll
        for (int i = 0; i < 4; i++) {
            int idx = tid + i * 256, row = idx >> 3, seg = idx & 7;
            CPA(base + STG_A + row * ROWB + seg * 16, Bp + (size_t)row * KB + s * 128 + seg * 16);
        }
        CPC();
    }

    int sbuf = 0, wbuf = 2;
    for (int c = 0; c < NCH; c++) {
        if (c == NCH - 1) { CPW0(); } else { CPW1(); }
        __syncthreads();
        if (c + 2 < NCH) {
            uint32_t base = sb + wbuf * STG;
            int ao = AOFF(c + 2), bo = (c + 2) * 128;
#pragma unroll
            for (int i = 0; i < 4; i++) {
                int idx = tid + i * 256, row = idx >> 3, seg = idx & 7;
                CPA(base + row * ROWB + seg * 16, Ap + (size_t)row * KA + ao + seg * 16);
            }
#pragma unroll
            for (int i = 0; i < 4; i++) {
                int idx = tid + i * 256, row = idx >> 3, seg = idx & 7;
                CPA(base + STG_A + row * ROWB + seg * 16, Bp + (size_t)row * KB + bo + seg * 16);
            }
            CPC();
        }
        uint32_t base = sb + sbuf * STG;
#pragma unroll
        for (int kk = 0; kk < 4; kk++) {
            uint32_t a[4][4], b[2][4];
#pragma unroll
            for (int mi = 0; mi < 4; mi++) LDSM4(a[mi], base + a_off[mi] + kk * 32);
#pragma unroll
            for (int p = 0; p < 2; p++) LDSM4(b[p], base + b_off[p] + kk * 32);
#pragma unroll
            for (int mi = 0; mi < 4; mi++)
#pragma unroll
                for (int g = 0; g < 4; g++)
                    IMMA(acc[mi][g], a[mi], b[g >> 1][g & 1], b[g >> 1][(g & 1) + 2]);
        }
        if (c == 3) {        // phase boundary: scale AhBh sum by 128
#pragma unroll
            for (int a = 0; a < 4; a++)
#pragma unroll
                for (int b = 0; b < 4; b++)
#pragma unroll
                    for (int e = 0; e < 4; e++) acc[a][b][e] *= 128;
        }
        sbuf = (sbuf == 2) ? 0 : sbuf + 1;
        wbuf = (wbuf == 2) ? 0 : wbuf + 1;
    }

    float sc = g_scl[aidx] * g_scl[bidx] * (1.0f / (127.0f * 127.0f * 128.0f));

    if (MODE <= 1) {
        float vmax = 0.0f;
#pragma unroll
        for (int mi = 0; mi < 4; mi++)
#pragma unroll
            for (int half = 0; half < 2; half++) {
                int row = m0 + wm * 64 + mi * 16 + (lane >> 2) + half * 8;
#pragma unroll
                for (int g = 0; g < 4; g++) {
                    int col = j0 + wn * 32 + g * 8 + (lane & 3) * 2;
                    float v0 = lrelu((float)acc[mi][g][half * 2]     * sc + __ldg(&bias[col]));
                    float v1 = lrelu((float)acc[mi][g][half * 2 + 1] * sc + __ldg(&bias[col + 1]));
                    vmax = fmaxf(vmax, fmaxf(fabsf(v0), fabsf(v1)));
                    *reinterpret_cast<float2*>(g_F + (size_t)row * Dd + col) = make_float2(v0, v1);
                }
            }
#pragma unroll
        for (int s = 16; s > 0; s >>= 1) vmax = fmaxf(vmax, __shfl_xor_sync(0xffffffffu, vmax, s));
        if (lane == 0) amax_atomic(vmax, &g_scl[oidx]);
    } else {
        float rs[4][2];
#pragma unroll
        for (int mi = 0; mi < 4; mi++)
#pragma unroll
            for (int half = 0; half < 2; half++) {
                float s = 0.0f;
#pragma unroll
                for (int g = 0; g < 4; g++) {
                    int col = j0 + wn * 32 + g * 8 + (lane & 3) * 2;
                    int bi = n * Hh + col;
                    s += lrelu((float)acc[mi][g][half * 2]     * sc + __ldg(&bias[bi]))     * __ldg(&wc2[bi]);
                    s += lrelu((float)acc[mi][g][half * 2 + 1] * sc + __ldg(&bias[bi + 1])) * __ldg(&wc2[bi + 1]);
                }
                s += __shfl_xor_sync(0xffffffffu, s, 1);
                s += __shfl_xor_sync(0xffffffffu, s, 2);
                rs[mi][half] = s;
            }
        __syncthreads();
        float* red = reinterpret_cast<float*>(smem);
        if ((lane & 3) == 0) {
#pragma unroll
            for (int mi = 0; mi < 4; mi++)
#pragma unroll
                for (int half = 0; half < 2; half++) {
                    int rl = wm * 64 + mi * 16 + (lane >> 2) + half * 8;
                    red[wn * 128 + rl] = rs[mi][half];
                }
        }
        __syncthreads();
        if (tid < 128) {
            float tot = red[tid] + red[128 + tid] + red[256 + tid] + red[384 + tid];
            g_part[((size_t)jt * M_TOT + m0 + tid) * Nn + n] = tot;
        }
    }
}

// ---------------------------------------------------------------------------
__global__ void k_fin(const float* __restrict__ bc2, float* __restrict__ out) {
    int i = blockIdx.x * blockDim.x + threadIdx.x;
    if (i >= M_TOT * Nn) return;
    int nn = i & 15;
    out[16384 + i] = g_part[i] + g_part[262144 + i] + g_part[2 * 262144 + i]
                   + g_part[3 * 262144 + i] + bc2[nn];
}
__global__ void k_sig(const float* __restrict__ bc2, float* __restrict__ out) {
    int i = blockIdx.x * blockDim.x + threadIdx.x;
    if (i >= Bsz * Nn) return;
    int b = i >> 4, nn = i & 15;
    size_t idx = ((size_t)nn * Bsz + b) * Nn + nn;
    float lg = g_part[idx] + g_part[262144 + idx] + g_part[2 * 262144 + idx]
             + g_part[3 * 262144 + idx] + bc2[nn];
    out[i] = 1.0f / (1.0f + expf(-lg));
}

// ---------------------------------------------------------------------------
extern "C" void kernel_launch(void* const* d_in, const int* in_sizes, int n_in,
                              void* d_out, int out_size) {
    const float* x   = (const float*)d_in[0];
    const float* Ws1 = (const float*)d_in[1];
    const float* bs1 = (const float*)d_in[2];
    const float* Ws2 = (const float*)d_in[3];
    const float* bs2 = (const float*)d_in[4];
    const float* Wc1 = (const float*)d_in[5];
    const float* bc1 = (const float*)d_in[6];
    const float* Wc2 = (const float*)d_in[7];
    const float* bc2 = (const float*)d_in[8];
    float* out = (float*)d_out;

    cudaFuncSetAttribute(k_imma<0>, cudaFuncAttributeMaxDynamicSharedMemorySize, SMEM_TOTAL);
    cudaFuncSetAttribute(k_imma<1>, cudaFuncAttributeMaxDynamicSharedMemorySize, SMEM_TOTAL);
    cudaFuncSetAttribute(k_imma<2>, cudaFuncAttributeMaxDynamicSharedMemorySize, SMEM_TOTAL);

    uint8_t *A0p, *A1p, *W1p, *W2p, *Wcp;
    cudaGetSymbolAddress((void**)&A0p, g_Aq0);
    cudaGetSymbolAddress((void**)&A1p, g_Aq1);
    cudaGetSymbolAddress((void**)&W1p, g_W1q);
    cudaGetSymbolAddress((void**)&W2p, g_W2q);
    cudaGetSymbolAddress((void**)&Wcp, g_Wcq);

    k_clear<<<1, 32>>>();
    k_absmax<<<256, 256>>>(x,   Bsz * Dd * Nn / 4, 0);
    k_absmax<<<64, 256>>>(Ws1, Dd * Dd / 4, 1);
    k_absmax<<<64, 256>>>(Ws2, Dd * Dd / 4, 2);
    k_absmax<<<256, 256>>>(Wc1, Nn * Dd * Hh / 4, 3);

    k_quant_w<<<dim3(16, 16, 18), dim3(32, 8)>>>(Ws1, Ws2, Wc1);
    k_quant_x<<<Bsz, 256>>>(x);

    k_imma<0><<<dim3(4, 128), 256, SMEM_TOTAL>>>(A0p, W1p, bs1, nullptr, 0, 1, 4);
    k_quant_a<<<(M_TOT * Dd / 4 + 255) / 256, 256>>>(4, A1p);
    k_imma<1><<<dim3(4, 128), 256, SMEM_TOTAL>>>(A1p, W2p, bs2, nullptr, 4, 2, 5);
    k_quant_a<<<(M_TOT * Dd / 4 + 255) / 256, 256>>>(5, A0p);
    k_imma<2><<<dim3(4, 16, 128), 256, SMEM_TOTAL>>>(A0p, Wcp, bc1, Wc2, 5, 3, 6);

    k_fin<<<(M_TOT * Nn + 255) / 256, 256>>>(bc2, out);
    k_sig<<<(Bsz * Nn + 255) / 256, 256>>>(bc2, out);
}

// round 6
// speedup vs baseline: 3.3191x; 3.3191x over previous
#include <cuda_runtime.h>
#include <cuda_fp16.h>
#include <cstdint>
#include <math.h>

#define Bsz 1024
#define Dd  512
#define Nn  16
#define Hh  512
#define M_TOT 16384
#define KAE  1024                // A row elems: [ah(512) | al(512)] fp16
#define KBE  512                 // B row elems: bh only
#define KS   64                  // K elems per pipeline stage (128 B)
#define NCH  16                  // 8 (ah) + 8 (al) chunks
#define TM   128
#define TN   128
#define ROWB 144                 // smem row stride (128B data + 16B pad)
#define STG_A (TM * ROWB)
#define STG_B (TN * ROWB)
#define STG   (STG_A + STG_B)    // 36864
#define SMEM_TOTAL (3 * STG)     // 110592

// ---------------- scratch ----------------
__device__ __half g_A0[(size_t)M_TOT * KAE];
__device__ __half g_A1[(size_t)M_TOT * KAE];
__device__ __half g_W1[(size_t)Dd * KBE];
__device__ __half g_W2[(size_t)Dd * KBE];
__device__ __half g_Wc[(size_t)Nn * Hh * KBE];
__device__ float  g_part[4 * (size_t)M_TOT * Nn];

// ---------------- helpers ----------------
static __device__ __forceinline__ uint32_t smem_u32(const void* p) {
    uint32_t a;
    asm("{ .reg .u64 t; cvta.to.shared.u64 t, %1; cvt.u32.u64 %0, t; }" : "=r"(a) : "l"(p));
    return a;
}
static __device__ __forceinline__ float lrelu(float v) { return v >= 0.0f ? v : 0.1f * v; }
static __device__ __forceinline__ void hsplit(float v, __half& h, __half& l) {
    h = __float2half_rn(v);
    l = __float2half_rn(v - __half2float(h));
}

#define LDSM4(r, a)                                                                     \
    asm volatile("ldmatrix.sync.aligned.m8n8.x4.shared.b16 {%0,%1,%2,%3}, [%4];"        \
                 : "=r"((r)[0]), "=r"((r)[1]), "=r"((r)[2]), "=r"((r)[3]) : "r"(a))
#define MMA(d, a, b0, b1)                                                               \
    asm volatile("mma.sync.aligned.m16n8k16.row.col.f32.f16.f16.f32 "                   \
                 "{%0,%1,%2,%3},{%4,%5,%6,%7},{%8,%9},{%0,%1,%2,%3};"                   \
                 : "+f"((d)[0]), "+f"((d)[1]), "+f"((d)[2]), "+f"((d)[3])               \
                 : "r"((a)[0]), "r"((a)[1]), "r"((a)[2]), "r"((a)[3]), "r"(b0), "r"(b1))
#define CPA(dst, src) asm volatile("cp.async.cg.shared.global [%0], [%1], 16;" :: "r"(dst), "l"(src))
#define CPC()  asm volatile("cp.async.commit_group;" ::: "memory")
#define CPW1() asm volatile("cp.async.wait_group 1;" ::: "memory")
#define CPW0() asm volatile("cp.async.wait_group 0;" ::: "memory")

// ---------------------------------------------------------------------------
// convert x (B, D, N) fp32 -> g_A0[m = n*B + b] rows [ah | al]
// ---------------------------------------------------------------------------
__global__ void k_convert_x(const float* __restrict__ x) {
    __shared__ float sm[Dd * 17];
    int b = blockIdx.x;
    const float4* xp = reinterpret_cast<const float4*>(x + (size_t)b * Dd * Nn);
    for (int v = threadIdx.x; v < 2048; v += blockDim.x) {
        float4 q = xp[v];
        int d = v >> 2, n0 = (v & 3) * 4;
        sm[d * 17 + n0 + 0] = q.x; sm[d * 17 + n0 + 1] = q.y;
        sm[d * 17 + n0 + 2] = q.z; sm[d * 17 + n0 + 3] = q.w;
    }
    __syncthreads();
    int d0 = (threadIdx.x & 127) * 4;
    int nh = threadIdx.x >> 7;                  // 0 or 1
    for (int nb = 0; nb < Nn; nb += 2) {
        int n = nb + nh;
        __half* row = g_A0 + (size_t)(n * Bsz + b) * KAE;
        __half h[4], l[4];
#pragma unroll
        for (int e = 0; e < 4; e++) hsplit(sm[(d0 + e) * 17 + n], h[e], l[e]);
        *reinterpret_cast<uint2*>(row + d0)       = *reinterpret_cast<uint2*>(h);
        *reinterpret_cast<uint2*>(row + 512 + d0) = *reinterpret_cast<uint2*>(l);
    }
}

// ---------------------------------------------------------------------------
// convert weights W[k][j] -> B'[j][k] = fp16(W) transposed (hi only)
// z = 0: Ws1 ; z = 1: Ws2 ; z >= 2: Wc1[n = z-2]
// ---------------------------------------------------------------------------
__global__ void k_convert_w(const float* __restrict__ Ws1,
                            const float* __restrict__ Ws2,
                            const float* __restrict__ Wc1) {
    __shared__ float sm[32][33];
    int z = blockIdx.z;
    const float* in;
    __half* out;
    if (z == 0)      { in = Ws1; out = g_W1; }
    else if (z == 1) { in = Ws2; out = g_W2; }
    else             { in = Wc1 + (size_t)(z - 2) * Dd * Hh;
                       out = g_Wc + (size_t)(z - 2) * Hh * KBE; }
    int k0 = blockIdx.x * 32, j0 = blockIdx.y * 32;
    int tx = threadIdx.x, ty = threadIdx.y;
#pragma unroll
    for (int i = 0; i < 4; i++) {
        int r = ty + i * 8;
        sm[r][tx] = in[(size_t)(k0 + r) * Dd + j0 + tx];
    }
    __syncthreads();
#pragma unroll
    for (int i = 0; i < 4; i++) {
        int r = ty + i * 8;                 // local j
        out[(size_t)(j0 + r) * KBE + k0 + tx] = __float2half_rn(sm[tx][r]);
    }
}

// ---------------------------------------------------------------------------
// fp16 HMMA GEMM: CTA 128x128, warp 64x32, K' = 1024 (2-term split).
// Chunk c: A cols c*64 ; B cols (c&7)*64 (B reused for the low-part pass).
// 3-stage cp.async pipeline + register-fragment pipelining.
// MODE 0/1: Aout = hsplit(lrelu(acc + bias))
// MODE 2:   g_part[jt][m][n] = sum_h lrelu(acc + bc1) * Wc2
// ---------------------------------------------------------------------------
template <int MODE>
__global__ void __launch_bounds__(256, 2)
k_mma(const __half* __restrict__ Ag,
      const __half* __restrict__ Bg,
      const float* __restrict__ bias,
      const float* __restrict__ wc2,
      __half* __restrict__ Aout) {
    extern __shared__ char smem[];
    uint32_t sb = smem_u32(smem);
    int tid = threadIdx.x, lane = tid & 31, wid = tid >> 5;
    int wm = wid & 1, wn = wid >> 1;

    int jt = blockIdx.x;
    int n  = (MODE == 2) ? blockIdx.y : 0;
    int m0 = ((MODE == 2) ? blockIdx.z : blockIdx.y) * TM;
    int j0 = jt * TN;

    const __half* Ap = Ag + (size_t)m0 * KAE;
    const __half* Bp = Bg + ((size_t)n * Hh + j0) * KBE;

    float acc[4][4][4];
#pragma unroll
    for (int a = 0; a < 4; a++)
#pragma unroll
        for (int b = 0; b < 4; b++)
#pragma unroll
            for (int c = 0; c < 4; c++) acc[a][b][c] = 0.0f;

    uint32_t a_off[4], b_off[2];
#pragma unroll
    for (int mi = 0; mi < 4; mi++)
        a_off[mi] = (uint32_t)((wm * 64 + mi * 16 + (lane & 15)) * ROWB + (lane >> 4) * 16);
#pragma unroll
    for (int p = 0; p < 2; p++)
        b_off[p] = (uint32_t)(STG_A + (wn * 32 + p * 16 + (lane & 15)) * ROWB + (lane >> 4) * 16);

    // ---- prologue: stages 0, 1 ----
#pragma unroll
    for (int s = 0; s < 2; s++) {
        uint32_t base = sb + s * STG;
#pragma unroll
        for (int i = 0; i < 4; i++) {
            int idx = tid + i * 256, row = idx >> 3, seg = idx & 7;
            CPA(base + row * ROWB + seg * 16, Ap + (size_t)row * KAE + s * KS + seg * 8);
        }
#pragma unroll
        for (int i = 0; i < 4; i++) {
            int idx = tid + i * 256, row = idx >> 3, seg = idx & 7;
            CPA(base + STG_A + row * ROWB + seg * 16, Bp + (size_t)row * KBE + s * KS + seg * 8);
        }
        CPC();
    }

    int sbuf = 0, wbuf = 2;
    for (int c = 0; c < NCH; c++) {
        if (c == NCH - 1) { CPW0(); } else { CPW1(); }
        __syncthreads();
        if (c + 2 < NCH) {
            uint32_t base = sb + wbuf * STG;
            int ao = (c + 2) * KS, bo = ((c + 2) & 7) * KS;
#pragma unroll
            for (int i = 0; i < 4; i++) {
                int idx = tid + i * 256, row = idx >> 3, seg = idx & 7;
                CPA(base + row * ROWB + seg * 16, Ap + (size_t)row * KAE + ao + seg * 8);
            }
#pragma unroll
            for (int i = 0; i < 4; i++) {
                int idx = tid + i * 256, row = idx >> 3, seg = idx & 7;
                CPA(base + STG_A + row * ROWB + seg * 16, Bp + (size_t)row * KBE + bo + seg * 8);
            }
            CPC();
        }
        uint32_t base = sb + sbuf * STG;
        // register-fragment pipeline over kk = 0..3
        uint32_t fa[2][4][4], fb[2][4];
#pragma unroll
        for (int mi = 0; mi < 4; mi++) LDSM4(fa[0][mi], base + a_off[mi]);
#pragma unroll
        for (int kk = 0; kk < 4; kk++) {
#pragma unroll
            for (int p = 0; p < 2; p++) LDSM4(fb[p], base + b_off[p] + kk * 32);
            if (kk < 3) {
#pragma unroll
                for (int mi = 0; mi < 4; mi++)
                    LDSM4(fa[(kk + 1) & 1][mi], base + a_off[mi] + (kk + 1) * 32);
            }
#pragma unroll
            for (int mi = 0; mi < 4; mi++)
#pragma unroll
                for (int p = 0; p < 2; p++) {
                    MMA(acc[mi][2 * p],     fa[kk & 1][mi], fb[p][0], fb[p][2]);
                    MMA(acc[mi][2 * p + 1], fa[kk & 1][mi], fb[p][1], fb[p][3]);
                }
        }
        sbuf = (sbuf == 2) ? 0 : sbuf + 1;
        wbuf = (wbuf == 2) ? 0 : wbuf + 1;
    }

    if (MODE <= 1) {
#pragma unroll
        for (int mi = 0; mi < 4; mi++)
#pragma unroll
            for (int half = 0; half < 2; half++) {
                int row = m0 + wm * 64 + mi * 16 + (lane >> 2) + half * 8;
                __half* rowp = Aout + (size_t)row * KAE;
#pragma unroll
                for (int g = 0; g < 4; g++) {
                    int col = j0 + wn * 32 + g * 8 + (lane & 3) * 2;
                    float v0 = lrelu(acc[mi][g][half * 2]     + __ldg(&bias[col]));
                    float v1 = lrelu(acc[mi][g][half * 2 + 1] + __ldg(&bias[col + 1]));
                    __half h0, l0, h1, l1;
                    hsplit(v0, h0, l0);
                    hsplit(v1, h1, l1);
                    __half hh[2] = {h0, h1}, ll[2] = {l0, l1};
                    *reinterpret_cast<uint32_t*>(rowp + col)       = *reinterpret_cast<uint32_t*>(hh);
                    *reinterpret_cast<uint32_t*>(rowp + 512 + col) = *reinterpret_cast<uint32_t*>(ll);
                }
            }
    } else {
        float rs[4][2];
#pragma unroll
        for (int mi = 0; mi < 4; mi++)
#pragma unroll
            for (int half = 0; half < 2; half++) {
                float s = 0.0f;
#pragma unroll
                for (int g = 0; g < 4; g++) {
                    int col = j0 + wn * 32 + g * 8 + (lane & 3) * 2;
                    int bi = n * Hh + col;
                    s += lrelu(acc[mi][g][half * 2]     + __ldg(&bias[bi]))     * __ldg(&wc2[bi]);
                    s += lrelu(acc[mi][g][half * 2 + 1] + __ldg(&bias[bi + 1])) * __ldg(&wc2[bi + 1]);
                }
                s += __shfl_xor_sync(0xffffffffu, s, 1);
                s += __shfl_xor_sync(0xffffffffu, s, 2);
                rs[mi][half] = s;
            }
        __syncthreads();
        float* red = reinterpret_cast<float*>(smem);
        if ((lane & 3) == 0) {
#pragma unroll
            for (int mi = 0; mi < 4; mi++)
#pragma unroll
                for (int half = 0; half < 2; half++) {
                    int rl = wm * 64 + mi * 16 + (lane >> 2) + half * 8;
                    red[wn * 128 + rl] = rs[mi][half];
                }
        }
        __syncthreads();
        if (tid < 128) {
            float tot = red[tid] + red[128 + tid] + red[256 + tid] + red[384 + tid];
            g_part[((size_t)jt * M_TOT + m0 + tid) * Nn + n] = tot;
        }
    }
}

// ---------------------------------------------------------------------------
__global__ void k_fin(const float* __restrict__ bc2, float* __restrict__ out) {
    int i = blockIdx.x * blockDim.x + threadIdx.x;
    if (i >= M_TOT * Nn) return;
    int nn = i & 15;
    out[16384 + i] = g_part[i] + g_part[262144 + i] + g_part[2 * 262144 + i]
                   + g_part[3 * 262144 + i] + bc2[nn];
}
__global__ void k_sig(const float* __restrict__ bc2, float* __restrict__ out) {
    int i = blockIdx.x * blockDim.x + threadIdx.x;
    if (i >= Bsz * Nn) return;
    int b = i >> 4, nn = i & 15;
    size_t idx = ((size_t)nn * Bsz + b) * Nn + nn;
    float lg = g_part[idx] + g_part[262144 + idx] + g_part[2 * 262144 + idx]
             + g_part[3 * 262144 + idx] + bc2[nn];
    out[i] = 1.0f / (1.0f + expf(-lg));
}

// ---------------------------------------------------------------------------
extern "C" void kernel_launch(void* const* d_in, const int* in_sizes, int n_in,
                              void* d_out, int out_size) {
    const float* x   = (const float*)d_in[0];
    const float* Ws1 = (const float*)d_in[1];
    const float* bs1 = (const float*)d_in[2];
    const float* Ws2 = (const float*)d_in[3];
    const float* bs2 = (const float*)d_in[4];
    const float* Wc1 = (const float*)d_in[5];
    const float* bc1 = (const float*)d_in[6];
    const float* Wc2 = (const float*)d_in[7];
    const float* bc2 = (const float*)d_in[8];
    float* out = (float*)d_out;

    cudaFuncSetAttribute(k_mma<0>, cudaFuncAttributeMaxDynamicSharedMemorySize, SMEM_TOTAL);
    cudaFuncSetAttribute(k_mma<1>, cudaFuncAttributeMaxDynamicSharedMemorySize, SMEM_TOTAL);
    cudaFuncSetAttribute(k_mma<2>, cudaFuncAttributeMaxDynamicSharedMemorySize, SMEM_TOTAL);

    __half *A0p, *A1p, *W1p, *W2p, *Wcp;
    cudaGetSymbolAddress((void**)&A0p, g_A0);
    cudaGetSymbolAddress((void**)&A1p, g_A1);
    cudaGetSymbolAddress((void**)&W1p, g_W1);
    cudaGetSymbolAddress((void**)&W2p, g_W2);
    cudaGetSymbolAddress((void**)&Wcp, g_Wc);

    k_convert_x<<<Bsz, 256>>>(x);
    k_convert_w<<<dim3(16, 16, 18), dim3(32, 8)>>>(Ws1, Ws2, Wc1);

    k_mma<0><<<dim3(4, 128), 256, SMEM_TOTAL>>>(A0p, W1p, bs1, nullptr, A1p);
    k_mma<1><<<dim3(4, 128), 256, SMEM_TOTAL>>>(A1p, W2p, bs2, nullptr, A0p);
    k_mma<2><<<dim3(4, 16, 128), 256, SMEM_TOTAL>>>(A0p, Wcp, bc1, Wc2, nullptr);

    k_fin<<<(M_TOT * Nn + 255) / 256, 256>>>(bc2, out);
    k_sig<<<(Bsz * Nn + 255) / 256, 256>>>(bc2, out);
}

// round 7
// speedup vs baseline: 3.4067x; 1.0264x over previous
#include <cuda_runtime.h>
#include <cuda_fp16.h>
#include <cstdint>
#include <math.h>

#define Bsz 1024
#define Dd  512
#define Nn  16
#define Hh  512
#define M_TOT 16384
#define KAE  1024                // A row elems: [ah(512) | al(512)] fp16
#define KBE  512                 // B row elems: bh only
#define KS   64                  // K elems per chunk
#define NCH  8                   // 8 merged hi+lo chunks
#define TM   64
#define TN   128
#define ROWB 144                 // smem row stride (128B data + 16B pad)
#define SA_LO (TM * ROWB)        // 9216
#define SB    (2 * TM * ROWB)    // 18432
#define STG   (SB + TN * ROWB)   // 36864
#define SMEM_TOTAL (3 * STG)     // 110592

// ---------------- scratch ----------------
__device__ __half g_A0[(size_t)M_TOT * KAE];
__device__ __half g_A1[(size_t)M_TOT * KAE];
__device__ __half g_W1[(size_t)Dd * KBE];
__device__ __half g_W2[(size_t)Dd * KBE];
__device__ __half g_Wc[(size_t)Nn * Hh * KBE];
__device__ float  g_part[4 * (size_t)M_TOT * Nn];

// ---------------- helpers ----------------
static __device__ __forceinline__ uint32_t smem_u32(const void* p) {
    uint32_t a;
    asm("{ .reg .u64 t; cvta.to.shared.u64 t, %1; cvt.u32.u64 %0, t; }" : "=r"(a) : "l"(p));
    return a;
}
static __device__ __forceinline__ float lrelu(float v) { return v >= 0.0f ? v : 0.1f * v; }
static __device__ __forceinline__ void hsplit(float v, __half& h, __half& l) {
    h = __float2half_rn(v);
    l = __float2half_rn(v - __half2float(h));
}

#define LDSM4(r, a)                                                                     \
    asm volatile("ldmatrix.sync.aligned.m8n8.x4.shared.b16 {%0,%1,%2,%3}, [%4];"        \
                 : "=r"((r)[0]), "=r"((r)[1]), "=r"((r)[2]), "=r"((r)[3]) : "r"(a))
#define MMA(d, a, b0, b1)                                                               \
    asm volatile("mma.sync.aligned.m16n8k16.row.col.f32.f16.f16.f32 "                   \
                 "{%0,%1,%2,%3},{%4,%5,%6,%7},{%8,%9},{%0,%1,%2,%3};"                   \
                 : "+f"((d)[0]), "+f"((d)[1]), "+f"((d)[2]), "+f"((d)[3])               \
                 : "r"((a)[0]), "r"((a)[1]), "r"((a)[2]), "r"((a)[3]), "r"(b0), "r"(b1))
#define MMAH(d, a, b0, b1)                                                              \
    asm volatile("mma.sync.aligned.m16n8k16.row.col.f16.f16.f16.f16 "                   \
                 "{%0,%1},{%2,%3,%4,%5},{%6,%7},{%0,%1};"                               \
                 : "+r"((d)[0]), "+r"((d)[1])                                           \
                 : "r"((a)[0]), "r"((a)[1]), "r"((a)[2]), "r"((a)[3]), "r"(b0), "r"(b1))
#define CPA(dst, src) asm volatile("cp.async.cg.shared.global [%0], [%1], 16;" :: "r"(dst), "l"(src))
#define CPC()  asm volatile("cp.async.commit_group;" ::: "memory")
#define CPW1() asm volatile("cp.async.wait_group 1;" ::: "memory")
#define CPW0() asm volatile("cp.async.wait_group 0;" ::: "memory")

// ---------------------------------------------------------------------------
// convert x (B, D, N) fp32 -> g_A0[m = n*B + b] rows [ah | al]
// ---------------------------------------------------------------------------
__global__ void k_convert_x(const float* __restrict__ x) {
    __shared__ float sm[Dd * 17];
    int b = blockIdx.x;
    const float4* xp = reinterpret_cast<const float4*>(x + (size_t)b * Dd * Nn);
    for (int v = threadIdx.x; v < 2048; v += blockDim.x) {
        float4 q = xp[v];
        int d = v >> 2, n0 = (v & 3) * 4;
        sm[d * 17 + n0 + 0] = q.x; sm[d * 17 + n0 + 1] = q.y;
        sm[d * 17 + n0 + 2] = q.z; sm[d * 17 + n0 + 3] = q.w;
    }
    __syncthreads();
    int d0 = (threadIdx.x & 127) * 4;
    int nh = threadIdx.x >> 7;
    for (int nb = 0; nb < Nn; nb += 2) {
        int n = nb + nh;
        __half* row = g_A0 + (size_t)(n * Bsz + b) * KAE;
        __half h[4], l[4];
#pragma unroll
        for (int e = 0; e < 4; e++) hsplit(sm[(d0 + e) * 17 + n], h[e], l[e]);
        *reinterpret_cast<uint2*>(row + d0)       = *reinterpret_cast<uint2*>(h);
        *reinterpret_cast<uint2*>(row + 512 + d0) = *reinterpret_cast<uint2*>(l);
    }
}

// ---------------------------------------------------------------------------
// convert weights W[k][j] -> B'[j][k] fp16 transposed
// ---------------------------------------------------------------------------
__global__ void k_convert_w(const float* __restrict__ Ws1,
                            const float* __restrict__ Ws2,
                            const float* __restrict__ Wc1) {
    __shared__ float sm[32][33];
    int z = blockIdx.z;
    const float* in;
    __half* out;
    if (z == 0)      { in = Ws1; out = g_W1; }
    else if (z == 1) { in = Ws2; out = g_W2; }
    else             { in = Wc1 + (size_t)(z - 2) * Dd * Hh;
                       out = g_Wc + (size_t)(z - 2) * Hh * KBE; }
    int k0 = blockIdx.x * 32, j0 = blockIdx.y * 32;
    int tx = threadIdx.x, ty = threadIdx.y;
#pragma unroll
    for (int i = 0; i < 4; i++) {
        int r = ty + i * 8;
        sm[r][tx] = in[(size_t)(k0 + r) * Dd + j0 + tx];
    }
    __syncthreads();
#pragma unroll
    for (int i = 0; i < 4; i++) {
        int r = ty + i * 8;
        out[(size_t)(j0 + r) * KBE + k0 + tx] = __float2half_rn(sm[tx][r]);
    }
}

// ---------------------------------------------------------------------------
// fp16 HMMA GEMM: CTA 64x128, warp 32x32 (wm = wid&1, wn = wid>>1).
// 8 merged chunks: each stages A-hi, A-lo, B; hi -> fp32 acc, lo -> fp16 acc.
// 3-stage cp.async pipeline.
// MODE 0/1: Aout = hsplit(lrelu(acc + bias))
// MODE 2:   g_part[jt][m][n] = sum_h lrelu(acc + bc1) * Wc2
// ---------------------------------------------------------------------------
template <int MODE>
__global__ void __launch_bounds__(256, 2)
k_mma(const __half* __restrict__ Ag,
      const __half* __restrict__ Bg,
      const float* __restrict__ bias,
      const float* __restrict__ wc2,
      __half* __restrict__ Aout) {
    extern __shared__ char smem[];
    uint32_t sb = smem_u32(smem);
    int tid = threadIdx.x, lane = tid & 31, wid = tid >> 5;
    int wm = wid & 1, wn = wid >> 1;

    int jt = blockIdx.x;
    int n  = (MODE == 2) ? blockIdx.y : 0;
    int m0 = ((MODE == 2) ? blockIdx.z : blockIdx.y) * TM;
    int j0 = jt * TN;

    const __half* Ap = Ag + (size_t)m0 * KAE;
    const __half* Bp = Bg + ((size_t)n * Hh + j0) * KBE;

    float    acc[2][4][4];
    uint32_t acc16[2][4][2];
#pragma unroll
    for (int a = 0; a < 2; a++)
#pragma unroll
        for (int b = 0; b < 4; b++) {
#pragma unroll
            for (int c = 0; c < 4; c++) acc[a][b][c] = 0.0f;
            acc16[a][b][0] = 0u; acc16[a][b][1] = 0u;
        }

    uint32_t ah_off[2], al_off[2], b_off[2];
#pragma unroll
    for (int mi = 0; mi < 2; mi++) {
        uint32_t r = (uint32_t)((wm * 32 + mi * 16 + (lane & 15)) * ROWB + (lane >> 4) * 16);
        ah_off[mi] = r;
        al_off[mi] = SA_LO + r;
    }
#pragma unroll
    for (int p = 0; p < 2; p++)
        b_off[p] = (uint32_t)(SB + (wn * 32 + p * 16 + (lane & 15)) * ROWB + (lane >> 4) * 16);

    // stage loader: A-hi (2 iters), A-lo (2 iters), B (4 iters)
#define STAGE_LOAD(base, c)                                                             \
    do {                                                                                \
        int ko = (c) * KS;                                                              \
        _Pragma("unroll")                                                               \
        for (int i = 0; i < 2; i++) {                                                   \
            int idx = tid + i * 256, row = idx >> 3, seg = idx & 7;                     \
            CPA((base) + row * ROWB + seg * 16, Ap + (size_t)row * KAE + ko + seg * 8); \
        }                                                                               \
        _Pragma("unroll")                                                               \
        for (int i = 0; i < 2; i++) {                                                   \
            int idx = tid + i * 256, row = idx >> 3, seg = idx & 7;                     \
            CPA((base) + SA_LO + row * ROWB + seg * 16,                                 \
                Ap + (size_t)row * KAE + 512 + ko + seg * 8);                           \
        }                                                                               \
        _Pragma("unroll")                                                               \
        for (int i = 0; i < 4; i++) {                                                   \
            int idx = tid + i * 256, row = idx >> 3, seg = idx & 7;                     \
            CPA((base) + SB + row * ROWB + seg * 16,                                    \
                Bp + (size_t)row * KBE + ko + seg * 8);                                 \
        }                                                                               \
        CPC();                                                                          \
    } while (0)

    STAGE_LOAD(sb, 0);
    STAGE_LOAD(sb + STG, 1);

    int sbuf = 0, wbuf = 2;
    for (int c = 0; c < NCH; c++) {
        if (c == NCH - 1) { CPW0(); } else { CPW1(); }
        __syncthreads();
        if (c + 2 < NCH) {
            uint32_t base = sb + wbuf * STG;
            STAGE_LOAD(base, c + 2);
        }
        uint32_t base = sb + sbuf * STG;
#pragma unroll
        for (int kk = 0; kk < 4; kk++) {
            uint32_t fb[2][4], fh[2][4], fl[2][4];
#pragma unroll
            for (int p = 0; p < 2; p++) LDSM4(fb[p], base + b_off[p] + kk * 32);
#pragma unroll
            for (int mi = 0; mi < 2; mi++) LDSM4(fh[mi], base + ah_off[mi] + kk * 32);
#pragma unroll
            for (int mi = 0; mi < 2; mi++) LDSM4(fl[mi], base + al_off[mi] + kk * 32);
#pragma unroll
            for (int mi = 0; mi < 2; mi++)
#pragma unroll
                for (int p = 0; p < 2; p++) {
                    MMA(acc[mi][2 * p],     fh[mi], fb[p][0], fb[p][2]);
                    MMA(acc[mi][2 * p + 1], fh[mi], fb[p][1], fb[p][3]);
                    MMAH(acc16[mi][2 * p],     fl[mi], fb[p][0], fb[p][2]);
                    MMAH(acc16[mi][2 * p + 1], fl[mi], fb[p][1], fb[p][3]);
                }
        }
        sbuf = (sbuf == 2) ? 0 : sbuf + 1;
        wbuf = (wbuf == 2) ? 0 : wbuf + 1;
    }
#undef STAGE_LOAD

    if (MODE <= 1) {
#pragma unroll
        for (int mi = 0; mi < 2; mi++)
#pragma unroll
            for (int half = 0; half < 2; half++) {
                int row = m0 + wm * 32 + mi * 16 + (lane >> 2) + half * 8;
                __half* rowp = Aout + (size_t)row * KAE;
#pragma unroll
                for (int g = 0; g < 4; g++) {
                    int col = j0 + wn * 32 + g * 8 + (lane & 3) * 2;
                    __half2 c16 = *reinterpret_cast<__half2*>(&acc16[mi][g][half]);
                    float2 fc = __half22float2(c16);
                    float v0 = lrelu(acc[mi][g][half * 2]     + fc.x + __ldg(&bias[col]));
                    float v1 = lrelu(acc[mi][g][half * 2 + 1] + fc.y + __ldg(&bias[col + 1]));
                    __half h0, l0, h1, l1;
                    hsplit(v0, h0, l0);
                    hsplit(v1, h1, l1);
                    __half hh[2] = {h0, h1}, ll[2] = {l0, l1};
                    *reinterpret_cast<uint32_t*>(rowp + col)       = *reinterpret_cast<uint32_t*>(hh);
                    *reinterpret_cast<uint32_t*>(rowp + 512 + col) = *reinterpret_cast<uint32_t*>(ll);
                }
            }
    } else {
        float rs[2][2];
#pragma unroll
        for (int mi = 0; mi < 2; mi++)
#pragma unroll
            for (int half = 0; half < 2; half++) {
                float s = 0.0f;
#pragma unroll
                for (int g = 0; g < 4; g++) {
                    int col = j0 + wn * 32 + g * 8 + (lane & 3) * 2;
                    int bi = n * Hh + col;
                    __half2 c16 = *reinterpret_cast<__half2*>(&acc16[mi][g][half]);
                    float2 fc = __half22float2(c16);
                    s += lrelu(acc[mi][g][half * 2]     + fc.x + __ldg(&bias[bi]))     * __ldg(&wc2[bi]);
                    s += lrelu(acc[mi][g][half * 2 + 1] + fc.y + __ldg(&bias[bi + 1])) * __ldg(&wc2[bi + 1]);
                }
                s += __shfl_xor_sync(0xffffffffu, s, 1);
                s += __shfl_xor_sync(0xffffffffu, s, 2);
                rs[mi][half] = s;
            }
        __syncthreads();
        float* red = reinterpret_cast<float*>(smem);
        if ((lane & 3) == 0) {
#pragma unroll
            for (int mi = 0; mi < 2; mi++)
#pragma unroll
                for (int half = 0; half < 2; half++) {
                    int rl = wm * 32 + mi * 16 + (lane >> 2) + half * 8;
                    red[wn * 64 + rl] = rs[mi][half];
                }
        }
        __syncthreads();
        if (tid < 64) {
            float tot = red[tid] + red[64 + tid] + red[128 + tid] + red[192 + tid];
            g_part[((size_t)jt * M_TOT + m0 + tid) * Nn + n] = tot;
        }
    }
}

// ---------------------------------------------------------------------------
// finalize: full_out = sum parts + bc2 ; sigmoid diagonal for out (fused)
// ---------------------------------------------------------------------------
__global__ void k_fin(const float* __restrict__ bc2, float* __restrict__ out) {
    int i = blockIdx.x * blockDim.x + threadIdx.x;
    if (i >= M_TOT * Nn) return;
    int nn = i & 15;
    out[16384 + i] = g_part[i] + g_part[262144 + i] + g_part[2 * 262144 + i]
                   + g_part[3 * 262144 + i] + bc2[nn];
    if (i < Bsz * Nn) {
        int b = i >> 4;
        size_t idx = ((size_t)nn * Bsz + b) * Nn + nn;
        float lg = g_part[idx] + g_part[262144 + idx] + g_part[2 * 262144 + idx]
                 + g_part[3 * 262144 + idx] + bc2[nn];
        out[i] = 1.0f / (1.0f + expf(-lg));
    }
}

// ---------------------------------------------------------------------------
extern "C" void kernel_launch(void* const* d_in, const int* in_sizes, int n_in,
                              void* d_out, int out_size) {
    const float* x   = (const float*)d_in[0];
    const float* Ws1 = (const float*)d_in[1];
    const float* bs1 = (const float*)d_in[2];
    const float* Ws2 = (const float*)d_in[3];
    const float* bs2 = (const float*)d_in[4];
    const float* Wc1 = (const float*)d_in[5];
    const float* bc1 = (const float*)d_in[6];
    const float* Wc2 = (const float*)d_in[7];
    const float* bc2 = (const float*)d_in[8];
    float* out = (float*)d_out;

    cudaFuncSetAttribute(k_mma<0>, cudaFuncAttributeMaxDynamicSharedMemorySize, SMEM_TOTAL);
    cudaFuncSetAttribute(k_mma<1>, cudaFuncAttributeMaxDynamicSharedMemorySize, SMEM_TOTAL);
    cudaFuncSetAttribute(k_mma<2>, cudaFuncAttributeMaxDynamicSharedMemorySize, SMEM_TOTAL);

    __half *A0p, *A1p, *W1p, *W2p, *Wcp;
    cudaGetSymbolAddress((void**)&A0p, g_A0);
    cudaGetSymbolAddress((void**)&A1p, g_A1);
    cudaGetSymbolAddress((void**)&W1p, g_W1);
    cudaGetSymbolAddress((void**)&W2p, g_W2);
    cudaGetSymbolAddress((void**)&Wcp, g_Wc);

    k_convert_x<<<Bsz, 256>>>(x);
    k_convert_w<<<dim3(16, 16, 18), dim3(32, 8)>>>(Ws1, Ws2, Wc1);

    k_mma<0><<<dim3(4, 256), 256, SMEM_TOTAL>>>(A0p, W1p, bs1, nullptr, A1p);
    k_mma<1><<<dim3(4, 256), 256, SMEM_TOTAL>>>(A1p, W2p, bs2, nullptr, A0p);
    k_mma<2><<<dim3(4, 16, 256), 256, SMEM_TOTAL>>>(A0p, Wcp, bc1, Wc2, nullptr);

    k_fin<<<(M_TOT * Nn + 255) / 256, 256>>>(bc2, out);
}

// round 8
// speedup vs baseline: 5.7075x; 1.6754x over previous
#include <cuda_runtime.h>
#include <cuda_fp16.h>
#include <cstdint>
#include <math.h>

#define Bsz 1024
#define Dd  512
#define Nn  16
#define Hh  512
#define M_TOT 16384
#define KAE  1024                // A row elems: [ah(512) | al(512)] fp16
#define KBE  512                 // B row elems: bh only
#define KS   64                  // K elems per chunk
#define NCH  8
#define ROWB 144                 // smem row stride (128B data + 16B pad)

// ---- geometry for GEMM1/2 (64x128, split) ----
#define TM1   64
#define SA_LO (TM1 * ROWB)       // 9216
#define SB1   (2 * TM1 * ROWB)   // 18432
#define STG1  (SB1 + 128 * ROWB) // 36864
#define SMEM1 (3 * STG1)         // 110592

// ---- geometry for GEMM3 (128x128, hi only) ----
#define TM3   128
#define STG3_A (TM3 * ROWB)      // 18432
#define STG3   (2 * STG3_A)      // 36864
#define SMEM3  (3 * STG3)        // 110592

// ---------------- scratch ----------------
__device__ __half g_A0[(size_t)M_TOT * KAE];
__device__ __half g_A1[(size_t)M_TOT * KAE];
__device__ __half g_W1[(size_t)Dd * KBE];
__device__ __half g_W2[(size_t)Dd * KBE];
__device__ __half g_Wc[(size_t)Nn * Hh * KBE];
__device__ float  g_part[4 * (size_t)M_TOT * Nn];

// ---------------- helpers ----------------
static __device__ __forceinline__ uint32_t smem_u32(const void* p) {
    uint32_t a;
    asm("{ .reg .u64 t; cvta.to.shared.u64 t, %1; cvt.u32.u64 %0, t; }" : "=r"(a) : "l"(p));
    return a;
}
static __device__ __forceinline__ float lrelu(float v) { return v >= 0.0f ? v : 0.1f * v; }
static __device__ __forceinline__ void hsplit(float v, __half& h, __half& l) {
    h = __float2half_rn(v);
    l = __float2half_rn(v - __half2float(h));
}

#define LDSM4(r, a)                                                                     \
    asm volatile("ldmatrix.sync.aligned.m8n8.x4.shared.b16 {%0,%1,%2,%3}, [%4];"        \
                 : "=r"((r)[0]), "=r"((r)[1]), "=r"((r)[2]), "=r"((r)[3]) : "r"(a))
#define MMA(d, a, b0, b1)                                                               \
    asm volatile("mma.sync.aligned.m16n8k16.row.col.f32.f16.f16.f32 "                   \
                 "{%0,%1,%2,%3},{%4,%5,%6,%7},{%8,%9},{%0,%1,%2,%3};"                   \
                 : "+f"((d)[0]), "+f"((d)[1]), "+f"((d)[2]), "+f"((d)[3])               \
                 : "r"((a)[0]), "r"((a)[1]), "r"((a)[2]), "r"((a)[3]), "r"(b0), "r"(b1))
#define MMAH(d, a, b0, b1)                                                              \
    asm volatile("mma.sync.aligned.m16n8k16.row.col.f16.f16.f16.f16 "                   \
                 "{%0,%1},{%2,%3,%4,%5},{%6,%7},{%0,%1};"                               \
                 : "+r"((d)[0]), "+r"((d)[1])                                           \
                 : "r"((a)[0]), "r"((a)[1]), "r"((a)[2]), "r"((a)[3]), "r"(b0), "r"(b1))
#define CPA(dst, src) asm volatile("cp.async.cg.shared.global [%0], [%1], 16;" :: "r"(dst), "l"(src))
#define CPC()  asm volatile("cp.async.commit_group;" ::: "memory")
#define CPW1() asm volatile("cp.async.wait_group 1;" ::: "memory")
#define CPW0() asm volatile("cp.async.wait_group 0;" ::: "memory")

// ---------------------------------------------------------------------------
// convert x (B, D, N) fp32 -> g_A0[m = n*B + b] rows [ah | al]
// ---------------------------------------------------------------------------
__global__ void k_convert_x(const float* __restrict__ x) {
    __shared__ float sm[Dd * 17];
    int b = blockIdx.x;
    const float4* xp = reinterpret_cast<const float4*>(x + (size_t)b * Dd * Nn);
    for (int v = threadIdx.x; v < 2048; v += blockDim.x) {
        float4 q = xp[v];
        int d = v >> 2, n0 = (v & 3) * 4;
        sm[d * 17 + n0 + 0] = q.x; sm[d * 17 + n0 + 1] = q.y;
        sm[d * 17 + n0 + 2] = q.z; sm[d * 17 + n0 + 3] = q.w;
    }
    __syncthreads();
    int d0 = (threadIdx.x & 127) * 4;
    int nh = threadIdx.x >> 7;
    for (int nb = 0; nb < Nn; nb += 2) {
        int n = nb + nh;
        __half* row = g_A0 + (size_t)(n * Bsz + b) * KAE;
        __half h[4], l[4];
#pragma unroll
        for (int e = 0; e < 4; e++) hsplit(sm[(d0 + e) * 17 + n], h[e], l[e]);
        *reinterpret_cast<uint2*>(row + d0)       = *reinterpret_cast<uint2*>(h);
        *reinterpret_cast<uint2*>(row + 512 + d0) = *reinterpret_cast<uint2*>(l);
    }
}

// ---------------------------------------------------------------------------
// convert weights W[k][j] -> B'[j][k] fp16 transposed
// ---------------------------------------------------------------------------
__global__ void k_convert_w(const float* __restrict__ Ws1,
                            const float* __restrict__ Ws2,
                            const float* __restrict__ Wc1) {
    __shared__ float sm[32][33];
    int z = blockIdx.z;
    const float* in;
    __half* out;
    if (z == 0)      { in = Ws1; out = g_W1; }
    else if (z == 1) { in = Ws2; out = g_W2; }
    else             { in = Wc1 + (size_t)(z - 2) * Dd * Hh;
                       out = g_Wc + (size_t)(z - 2) * Hh * KBE; }
    int k0 = blockIdx.x * 32, j0 = blockIdx.y * 32;
    int tx = threadIdx.x, ty = threadIdx.y;
#pragma unroll
    for (int i = 0; i < 4; i++) {
        int r = ty + i * 8;
        sm[r][tx] = in[(size_t)(k0 + r) * Dd + j0 + tx];
    }
    __syncthreads();
#pragma unroll
    for (int i = 0; i < 4; i++) {
        int r = ty + i * 8;
        out[(size_t)(j0 + r) * KBE + k0 + tx] = __float2half_rn(sm[tx][r]);
    }
}

// ---------------------------------------------------------------------------
// GEMM1/2: CTA 64x128, warp 32x32. hi -> fp32 acc, lo -> fp16 acc (accurate).
// Aout = hsplit(lrelu(acc + bias))
// ---------------------------------------------------------------------------
__global__ void __launch_bounds__(256, 2)
k_mma12(const __half* __restrict__ Ag,
        const __half* __restrict__ Bg,
        const float* __restrict__ bias,
        __half* __restrict__ Aout) {
    extern __shared__ char smem[];
    uint32_t sb = smem_u32(smem);
    int tid = threadIdx.x, lane = tid & 31, wid = tid >> 5;
    int wm = wid & 1, wn = wid >> 1;

    int jt = blockIdx.x;
    int m0 = blockIdx.y * TM1;
    int j0 = jt * 128;

    const __half* Ap = Ag + (size_t)m0 * KAE;
    const __half* Bp = Bg + (size_t)j0 * KBE;

    float    acc[2][4][4];
    uint32_t acc16[2][4][2];
#pragma unroll
    for (int a = 0; a < 2; a++)
#pragma unroll
        for (int b = 0; b < 4; b++) {
#pragma unroll
            for (int c = 0; c < 4; c++) acc[a][b][c] = 0.0f;
            acc16[a][b][0] = 0u; acc16[a][b][1] = 0u;
        }

    uint32_t ah_off[2], al_off[2], b_off[2];
#pragma unroll
    for (int mi = 0; mi < 2; mi++) {
        uint32_t r = (uint32_t)((wm * 32 + mi * 16 + (lane & 15)) * ROWB + (lane >> 4) * 16);
        ah_off[mi] = r;
        al_off[mi] = SA_LO + r;
    }
#pragma unroll
    for (int p = 0; p < 2; p++)
        b_off[p] = (uint32_t)(SB1 + (wn * 32 + p * 16 + (lane & 15)) * ROWB + (lane >> 4) * 16);

#define STAGE_LOAD1(base, c)                                                            \
    do {                                                                                \
        int ko = (c) * KS;                                                              \
        _Pragma("unroll")                                                               \
        for (int i = 0; i < 2; i++) {                                                   \
            int idx = tid + i * 256, row = idx >> 3, seg = idx & 7;                     \
            CPA((base) + row * ROWB + seg * 16, Ap + (size_t)row * KAE + ko + seg * 8); \
        }                                                                               \
        _Pragma("unroll")                                                               \
        for (int i = 0; i < 2; i++) {                                                   \
            int idx = tid + i * 256, row = idx >> 3, seg = idx & 7;                     \
            CPA((base) + SA_LO + row * ROWB + seg * 16,                                 \
                Ap + (size_t)row * KAE + 512 + ko + seg * 8);                           \
        }                                                                               \
        _Pragma("unroll")                                                               \
        for (int i = 0; i < 4; i++) {                                                   \
            int idx = tid + i * 256, row = idx >> 3, seg = idx & 7;                     \
            CPA((base) + SB1 + row * ROWB + seg * 16,                                   \
                Bp + (size_t)row * KBE + ko + seg * 8);                                 \
        }                                                                               \
        CPC();                                                                          \
    } while (0)

    STAGE_LOAD1(sb, 0);
    STAGE_LOAD1(sb + STG1, 1);

    int sbuf = 0, wbuf = 2;
    for (int c = 0; c < NCH; c++) {
        if (c == NCH - 1) { CPW0(); } else { CPW1(); }
        __syncthreads();
        if (c + 2 < NCH) STAGE_LOAD1(sb + wbuf * STG1, c + 2);
        uint32_t base = sb + sbuf * STG1;
#pragma unroll
        for (int kk = 0; kk < 4; kk++) {
            uint32_t fb[2][4], fh[2][4], fl[2][4];
#pragma unroll
            for (int p = 0; p < 2; p++) LDSM4(fb[p], base + b_off[p] + kk * 32);
#pragma unroll
            for (int mi = 0; mi < 2; mi++) LDSM4(fh[mi], base + ah_off[mi] + kk * 32);
#pragma unroll
            for (int mi = 0; mi < 2; mi++) LDSM4(fl[mi], base + al_off[mi] + kk * 32);
#pragma unroll
            for (int mi = 0; mi < 2; mi++)
#pragma unroll
                for (int p = 0; p < 2; p++) {
                    MMA(acc[mi][2 * p],     fh[mi], fb[p][0], fb[p][2]);
                    MMA(acc[mi][2 * p + 1], fh[mi], fb[p][1], fb[p][3]);
                    MMAH(acc16[mi][2 * p],     fl[mi], fb[p][0], fb[p][2]);
                    MMAH(acc16[mi][2 * p + 1], fl[mi], fb[p][1], fb[p][3]);
                }
        }
        sbuf = (sbuf == 2) ? 0 : sbuf + 1;
        wbuf = (wbuf == 2) ? 0 : wbuf + 1;
    }
#undef STAGE_LOAD1

#pragma unroll
    for (int mi = 0; mi < 2; mi++)
#pragma unroll
        for (int half = 0; half < 2; half++) {
            int row = m0 + wm * 32 + mi * 16 + (lane >> 2) + half * 8;
            __half* rowp = Aout + (size_t)row * KAE;
#pragma unroll
            for (int g = 0; g < 4; g++) {
                int col = j0 + wn * 32 + g * 8 + (lane & 3) * 2;
                __half2 c16 = *reinterpret_cast<__half2*>(&acc16[mi][g][half]);
                float2 fc = __half22float2(c16);
                float v0 = lrelu(acc[mi][g][half * 2]     + fc.x + __ldg(&bias[col]));
                float v1 = lrelu(acc[mi][g][half * 2 + 1] + fc.y + __ldg(&bias[col + 1]));
                __half h0, l0, h1, l1;
                hsplit(v0, h0, l0);
                hsplit(v1, h1, l1);
                __half hh[2] = {h0, h1}, ll[2] = {l0, l1};
                *reinterpret_cast<uint32_t*>(rowp + col)       = *reinterpret_cast<uint32_t*>(hh);
                *reinterpret_cast<uint32_t*>(rowp + 512 + col) = *reinterpret_cast<uint32_t*>(ll);
            }
        }
}

// ---------------------------------------------------------------------------
// GEMM3: CTA 128x128, warp 64x32, hi-only (fp32 acc). K = 512.
// g_part[jt][m][n] = sum_h lrelu(acc + bc1[n,h]) * Wc2[n,h]
// ---------------------------------------------------------------------------
__global__ void __launch_bounds__(256, 2)
k_mma3(const __half* __restrict__ Ag,
       const __half* __restrict__ Bg,
       const float* __restrict__ bias,
       const float* __restrict__ wc2) {
    extern __shared__ char smem[];
    uint32_t sb = smem_u32(smem);
    int tid = threadIdx.x, lane = tid & 31, wid = tid >> 5;
    int wm = wid & 1, wn = wid >> 1;

    int jt = blockIdx.x;
    int n  = blockIdx.y;
    int m0 = blockIdx.z * TM3;
    int j0 = jt * 128;

    const __half* Ap = Ag + (size_t)m0 * KAE;
    const __half* Bp = Bg + ((size_t)n * Hh + j0) * KBE;

    float acc[4][4][4];
#pragma unroll
    for (int a = 0; a < 4; a++)
#pragma unroll
        for (int b = 0; b < 4; b++)
#pragma unroll
            for (int c = 0; c < 4; c++) acc[a][b][c] = 0.0f;

    uint32_t a_off[4], b_off[2];
#pragma unroll
    for (int mi = 0; mi < 4; mi++)
        a_off[mi] = (uint32_t)((wm * 64 + mi * 16 + (lane & 15)) * ROWB + (lane >> 4) * 16);
#pragma unroll
    for (int p = 0; p < 2; p++)
        b_off[p] = (uint32_t)(STG3_A + (wn * 32 + p * 16 + (lane & 15)) * ROWB + (lane >> 4) * 16);

#define STAGE_LOAD3(base, c)                                                            \
    do {                                                                                \
        int ko = (c) * KS;                                                              \
        _Pragma("unroll")                                                               \
        for (int i = 0; i < 4; i++) {                                                   \
            int idx = tid + i * 256, row = idx >> 3, seg = idx & 7;                     \
            CPA((base) + row * ROWB + seg * 16, Ap + (size_t)row * KAE + ko + seg * 8); \
        }                                                                               \
        _Pragma("unroll")                                                               \
        for (int i = 0; i < 4; i++) {                                                   \
            int idx = tid + i * 256, row = idx >> 3, seg = idx & 7;                     \
            CPA((base) + STG3_A + row * ROWB + seg * 16,                                \
                Bp + (size_t)row * KBE + ko + seg * 8);                                 \
        }                                                                               \
        CPC();                                                                          \
    } while (0)

    STAGE_LOAD3(sb, 0);
    STAGE_LOAD3(sb + STG3, 1);

    int sbuf = 0, wbuf = 2;
    for (int c = 0; c < NCH; c++) {
        if (c == NCH - 1) { CPW0(); } else { CPW1(); }
        __syncthreads();
        if (c + 2 < NCH) STAGE_LOAD3(sb + wbuf * STG3, c + 2);
        uint32_t base = sb + sbuf * STG3;
#pragma unroll
        for (int kk = 0; kk < 4; kk++) {
            uint32_t fa[4][4], fb[2][4];
#pragma unroll
            for (int p = 0; p < 2; p++) LDSM4(fb[p], base + b_off[p] + kk * 32);
#pragma unroll
            for (int mi = 0; mi < 4; mi++) LDSM4(fa[mi], base + a_off[mi] + kk * 32);
#pragma unroll
            for (int mi = 0; mi < 4; mi++)
#pragma unroll
                for (int p = 0; p < 2; p++) {
                    MMA(acc[mi][2 * p],     fa[mi], fb[p][0], fb[p][2]);
                    MMA(acc[mi][2 * p + 1], fa[mi], fb[p][1], fb[p][3]);
                }
        }
        sbuf = (sbuf == 2) ? 0 : sbuf + 1;
        wbuf = (wbuf == 2) ? 0 : wbuf + 1;
    }
#undef STAGE_LOAD3

    float rs[4][2];
#pragma unroll
    for (int mi = 0; mi < 4; mi++)
#pragma unroll
        for (int half = 0; half < 2; half++) {
            float s = 0.0f;
#pragma unroll
            for (int g = 0; g < 4; g++) {
                int col = j0 + wn * 32 + g * 8 + (lane & 3) * 2;
                int bi = n * Hh + col;
                s += lrelu(acc[mi][g][half * 2]     + __ldg(&bias[bi]))     * __ldg(&wc2[bi]);
                s += lrelu(acc[mi][g][half * 2 + 1] + __ldg(&bias[bi + 1])) * __ldg(&wc2[bi + 1]);
            }
            s += __shfl_xor_sync(0xffffffffu, s, 1);
            s += __shfl_xor_sync(0xffffffffu, s, 2);
            rs[mi][half] = s;
        }
    __syncthreads();
    float* red = reinterpret_cast<float*>(smem);
    if ((lane & 3) == 0) {
#pragma unroll
        for (int mi = 0; mi < 4; mi++)
#pragma unroll
            for (int half = 0; half < 2; half++) {
                int rl = wm * 64 + mi * 16 + (lane >> 2) + half * 8;
                red[wn * 128 + rl] = rs[mi][half];
            }
    }
    __syncthreads();
    if (tid < 128) {
        float tot = red[tid] + red[128 + tid] + red[256 + tid] + red[384 + tid];
        g_part[((size_t)jt * M_TOT + m0 + tid) * Nn + n] = tot;
    }
}

// ---------------------------------------------------------------------------
// finalize: full_out = sum parts + bc2 ; sigmoid diagonal for out (fused)
// ---------------------------------------------------------------------------
__global__ void k_fin(const float* __restrict__ bc2, float* __restrict__ out) {
    int i = blockIdx.x * blockDim.x + threadIdx.x;
    if (i >= M_TOT * Nn) return;
    int nn = i & 15;
    out[16384 + i] = g_part[i] + g_part[262144 + i] + g_part[2 * 262144 + i]
                   + g_part[3 * 262144 + i] + bc2[nn];
    if (i < Bsz * Nn) {
        int b = i >> 4;
        size_t idx = ((size_t)nn * Bsz + b) * Nn + nn;
        float lg = g_part[idx] + g_part[262144 + idx] + g_part[2 * 262144 + idx]
                 + g_part[3 * 262144 + idx] + bc2[nn];
        out[i] = 1.0f / (1.0f + expf(-lg));
    }
}

// ---------------------------------------------------------------------------
extern "C" void kernel_launch(void* const* d_in, const int* in_sizes, int n_in,
                              void* d_out, int out_size) {
    const float* x   = (const float*)d_in[0];
    const float* Ws1 = (const float*)d_in[1];
    const float* bs1 = (const float*)d_in[2];
    const float* Ws2 = (const float*)d_in[3];
    const float* bs2 = (const float*)d_in[4];
    const float* Wc1 = (const float*)d_in[5];
    const float* bc1 = (const float*)d_in[6];
    const float* Wc2 = (const float*)d_in[7];
    const float* bc2 = (const float*)d_in[8];
    float* out = (float*)d_out;

    cudaFuncSetAttribute(k_mma12, cudaFuncAttributeMaxDynamicSharedMemorySize, SMEM1);
    cudaFuncSetAttribute(k_mma3,  cudaFuncAttributeMaxDynamicSharedMemorySize, SMEM3);

    __half *A0p, *A1p, *W1p, *W2p, *Wcp;
    cudaGetSymbolAddress((void**)&A0p, g_A0);
    cudaGetSymbolAddress((void**)&A1p, g_A1);
    cudaGetSymbolAddress((void**)&W1p, g_W1);
    cudaGetSymbolAddress((void**)&W2p, g_W2);
    cudaGetSymbolAddress((void**)&Wcp, g_Wc);

    k_convert_x<<<Bsz, 256>>>(x);
    k_convert_w<<<dim3(16, 16, 18), dim3(32, 8)>>>(Ws1, Ws2, Wc1);

    k_mma12<<<dim3(4, 256), 256, SMEM1>>>(A0p, W1p, bs1, A1p);
    k_mma12<<<dim3(4, 256), 256, SMEM1>>>(A1p, W2p, bs2, A0p);
    k_mma3<<<dim3(4, 16, 128), 256, SMEM3>>>(A0p, Wcp, bc1, Wc2);

    k_fin<<<(M_TOT * Nn + 255) / 256, 256>>>(bc2, out);
}

// round 9
// speedup vs baseline: 5.9655x; 1.0452x over previous
#include <cuda_runtime.h>
#include <cuda_fp16.h>
#include <cstdint>
#include <math.h>

#define Bsz 1024
#define Dd  512
#define Nn  16
#define Hh  512
#define M_TOT 16384
#define KAE  512                 // A row elems (hi-only fp16)
#define KBE  512                 // B row elems
#define KS   64                  // K elems per chunk
#define NCH  8
#define ROWB 144                 // smem row stride (128B data + 16B pad)

// ---- GEMM1/2: CTA 128x128, 3-stage ----
#define TM12   128
#define STG12_A (TM12 * ROWB)    // 18432
#define STG12   (2 * STG12_A)    // 36864
#define SMEM12  (3 * STG12)      // 110592

// ---- GEMM3: A-resident, CTA 64 rows x 128 cols ----
#define TM3    64
#define SM3_A  (NCH * TM3 * ROWB)        // 73728 (8 chunk blocks)
#define SM3_B  73728                     // B buffers base
#define BBUF   (TM12 * ROWB)             // 18432 per B buffer
#define SM3_RED (SM3_B + 2 * BBUF)       // 110592
#define SMEM3  (SM3_RED + 1024)          // 111616

// ---------------- scratch ----------------
__device__ __half g_A0[(size_t)M_TOT * KAE];
__device__ __half g_A1[(size_t)M_TOT * KAE];
__device__ __half g_W1[(size_t)Dd * KBE];
__device__ __half g_W2[(size_t)Dd * KBE];
__device__ __half g_Wc[(size_t)Nn * Hh * KBE];
__device__ float  g_part[4 * (size_t)M_TOT * Nn];

// ---------------- helpers ----------------
static __device__ __forceinline__ uint32_t smem_u32(const void* p) {
    uint32_t a;
    asm("{ .reg .u64 t; cvta.to.shared.u64 t, %1; cvt.u32.u64 %0, t; }" : "=r"(a) : "l"(p));
    return a;
}
static __device__ __forceinline__ float lrelu(float v) { return v >= 0.0f ? v : 0.1f * v; }

#define LDSM4(r, a)                                                                     \
    asm volatile("ldmatrix.sync.aligned.m8n8.x4.shared.b16 {%0,%1,%2,%3}, [%4];"        \
                 : "=r"((r)[0]), "=r"((r)[1]), "=r"((r)[2]), "=r"((r)[3]) : "r"(a))
#define MMA(d, a, b0, b1)                                                               \
    asm volatile("mma.sync.aligned.m16n8k16.row.col.f32.f16.f16.f32 "                   \
                 "{%0,%1,%2,%3},{%4,%5,%6,%7},{%8,%9},{%0,%1,%2,%3};"                   \
                 : "+f"((d)[0]), "+f"((d)[1]), "+f"((d)[2]), "+f"((d)[3])               \
                 : "r"((a)[0]), "r"((a)[1]), "r"((a)[2]), "r"((a)[3]), "r"(b0), "r"(b1))
#define CPA(dst, src) asm volatile("cp.async.cg.shared.global [%0], [%1], 16;" :: "r"(dst), "l"(src))
#define CPC()  asm volatile("cp.async.commit_group;" ::: "memory")
#define CPW1() asm volatile("cp.async.wait_group 1;" ::: "memory")
#define CPW0() asm volatile("cp.async.wait_group 0;" ::: "memory")

// ---------------------------------------------------------------------------
// convert x (B, D, N) fp32 -> g_A0[m = n*B + b][d] fp16
// ---------------------------------------------------------------------------
__global__ void k_convert_x(const float* __restrict__ x) {
    __shared__ float sm[Dd * 17];
    int b = blockIdx.x;
    const float4* xp = reinterpret_cast<const float4*>(x + (size_t)b * Dd * Nn);
    for (int v = threadIdx.x; v < 2048; v += blockDim.x) {
        float4 q = xp[v];
        int d = v >> 2, n0 = (v & 3) * 4;
        sm[d * 17 + n0 + 0] = q.x; sm[d * 17 + n0 + 1] = q.y;
        sm[d * 17 + n0 + 2] = q.z; sm[d * 17 + n0 + 3] = q.w;
    }
    __syncthreads();
    int d0 = (threadIdx.x & 127) * 4;
    int nh = threadIdx.x >> 7;
    for (int nb = 0; nb < Nn; nb += 2) {
        int n = nb + nh;
        __half* row = g_A0 + (size_t)(n * Bsz + b) * KAE;
        __half h[4];
#pragma unroll
        for (int e = 0; e < 4; e++) h[e] = __float2half_rn(sm[(d0 + e) * 17 + n]);
        *reinterpret_cast<uint2*>(row + d0) = *reinterpret_cast<uint2*>(h);
    }
}

// ---------------------------------------------------------------------------
// convert weights W[k][j] -> B'[j][k] fp16 transposed
// ---------------------------------------------------------------------------
__global__ void k_convert_w(const float* __restrict__ Ws1,
                            const float* __restrict__ Ws2,
                            const float* __restrict__ Wc1) {
    __shared__ float sm[32][33];
    int z = blockIdx.z;
    const float* in;
    __half* out;
    if (z == 0)      { in = Ws1; out = g_W1; }
    else if (z == 1) { in = Ws2; out = g_W2; }
    else             { in = Wc1 + (size_t)(z - 2) * Dd * Hh;
                       out = g_Wc + (size_t)(z - 2) * Hh * KBE; }
    int k0 = blockIdx.x * 32, j0 = blockIdx.y * 32;
    int tx = threadIdx.x, ty = threadIdx.y;
#pragma unroll
    for (int i = 0; i < 4; i++) {
        int r = ty + i * 8;
        sm[r][tx] = in[(size_t)(k0 + r) * Dd + j0 + tx];
    }
    __syncthreads();
#pragma unroll
    for (int i = 0; i < 4; i++) {
        int r = ty + i * 8;
        out[(size_t)(j0 + r) * KBE + k0 + tx] = __float2half_rn(sm[tx][r]);
    }
}

// ---------------------------------------------------------------------------
// GEMM1/2: CTA 128x128, warp 64x32, hi-only. Aout = fp16(lrelu(acc + bias))
// ---------------------------------------------------------------------------
__global__ void __launch_bounds__(256, 2)
k_g12(const __half* __restrict__ Ag,
      const __half* __restrict__ Bg,
      const float* __restrict__ bias,
      __half* __restrict__ Aout) {
    extern __shared__ char smem[];
    uint32_t sb = smem_u32(smem);
    int tid = threadIdx.x, lane = tid & 31, wid = tid >> 5;
    int wm = wid & 1, wn = wid >> 1;

    int jt = blockIdx.x;
    int m0 = blockIdx.y * TM12;
    int j0 = jt * 128;

    const __half* Ap = Ag + (size_t)m0 * KAE;
    const __half* Bp = Bg + (size_t)j0 * KBE;

    float acc[4][4][4];
#pragma unroll
    for (int a = 0; a < 4; a++)
#pragma unroll
        for (int b = 0; b < 4; b++)
#pragma unroll
            for (int c = 0; c < 4; c++) acc[a][b][c] = 0.0f;

    uint32_t a_off[4], b_off[2];
#pragma unroll
    for (int mi = 0; mi < 4; mi++)
        a_off[mi] = (uint32_t)((wm * 64 + mi * 16 + (lane & 15)) * ROWB + (lane >> 4) * 16);
#pragma unroll
    for (int p = 0; p < 2; p++)
        b_off[p] = (uint32_t)(STG12_A + (wn * 32 + p * 16 + (lane & 15)) * ROWB + (lane >> 4) * 16);

#define STAGE_LOAD12(base, c)                                                           \
    do {                                                                                \
        int ko = (c) * KS;                                                              \
        _Pragma("unroll")                                                               \
        for (int i = 0; i < 4; i++) {                                                   \
            int idx = tid + i * 256, row = idx >> 3, seg = idx & 7;                     \
            CPA((base) + row * ROWB + seg * 16, Ap + (size_t)row * KAE + ko + seg * 8); \
        }                                                                               \
        _Pragma("unroll")                                                               \
        for (int i = 0; i < 4; i++) {                                                   \
            int idx = tid + i * 256, row = idx >> 3, seg = idx & 7;                     \
            CPA((base) + STG12_A + row * ROWB + seg * 16,                               \
                Bp + (size_t)row * KBE + ko + seg * 8);                                 \
        }                                                                               \
        CPC();                                                                          \
    } while (0)

    STAGE_LOAD12(sb, 0);
    STAGE_LOAD12(sb + STG12, 1);

    int sbuf = 0, wbuf = 2;
    for (int c = 0; c < NCH; c++) {
        if (c == NCH - 1) { CPW0(); } else { CPW1(); }
        __syncthreads();
        if (c + 2 < NCH) STAGE_LOAD12(sb + wbuf * STG12, c + 2);
        uint32_t base = sb + sbuf * STG12;
#pragma unroll
        for (int kk = 0; kk < 4; kk++) {
            uint32_t fa[4][4], fb[2][4];
#pragma unroll
            for (int p = 0; p < 2; p++) LDSM4(fb[p], base + b_off[p] + kk * 32);
#pragma unroll
            for (int mi = 0; mi < 4; mi++) LDSM4(fa[mi], base + a_off[mi] + kk * 32);
#pragma unroll
            for (int mi = 0; mi < 4; mi++)
#pragma unroll
                for (int p = 0; p < 2; p++) {
                    MMA(acc[mi][2 * p],     fa[mi], fb[p][0], fb[p][2]);
                    MMA(acc[mi][2 * p + 1], fa[mi], fb[p][1], fb[p][3]);
                }
        }
        sbuf = (sbuf == 2) ? 0 : sbuf + 1;
        wbuf = (wbuf == 2) ? 0 : wbuf + 1;
    }
#undef STAGE_LOAD12

#pragma unroll
    for (int mi = 0; mi < 4; mi++)
#pragma unroll
        for (int half = 0; half < 2; half++) {
            int row = m0 + wm * 64 + mi * 16 + (lane >> 2) + half * 8;
            __half* rowp = Aout + (size_t)row * KAE;
#pragma unroll
            for (int g = 0; g < 4; g++) {
                int col = j0 + wn * 32 + g * 8 + (lane & 3) * 2;
                float v0 = lrelu(acc[mi][g][half * 2]     + __ldg(&bias[col]));
                float v1 = lrelu(acc[mi][g][half * 2 + 1] + __ldg(&bias[col + 1]));
                __half hh[2] = {__float2half_rn(v0), __float2half_rn(v1)};
                *reinterpret_cast<uint32_t*>(rowp + col) = *reinterpret_cast<uint32_t*>(hh);
            }
        }
}

// ---------------------------------------------------------------------------
// GEMM3, A-resident: CTA holds full A tile (64 x 512) in smem, loops n=0..15,
// streams B (double-buffered, distance-1 prefetch). Warp tile 32x32.
// g_part[jt][m][n] = sum_h lrelu(acc + bc1[n,h]) * Wc2[n,h]
// ---------------------------------------------------------------------------
__global__ void __launch_bounds__(256, 2)
k_g3(const __half* __restrict__ Ag,
     const __half* __restrict__ Bg,
     const float* __restrict__ bias,
     const float* __restrict__ wc2) {
    extern __shared__ char smem[];
    uint32_t sb = smem_u32(smem);
    int tid = threadIdx.x, lane = tid & 31, wid = tid >> 5;
    int wm = wid & 1, wn = wid >> 1;

    int jt = blockIdx.x;
    int m0 = blockIdx.y * TM3;
    int j0 = jt * 128;

    const __half* Ap = Ag + (size_t)m0 * KAE;

    uint32_t a_base[2], b_base[2];
#pragma unroll
    for (int mi = 0; mi < 2; mi++)
        a_base[mi] = (uint32_t)((wm * 32 + mi * 16 + (lane & 15)) * ROWB + (lane >> 4) * 16);
#pragma unroll
    for (int p = 0; p < 2; p++)
        b_base[p] = (uint32_t)(SM3_B + (wn * 32 + p * 16 + (lane & 15)) * ROWB + (lane >> 4) * 16);

    // B chunk loader: step s -> n = s>>3, c = s&7, buffer s&1
#define LOAD_B(s)                                                                       \
    do {                                                                                \
        int _n = (s) >> 3, _c = (s) & 7;                                                \
        uint32_t _dst = sb + SM3_B + ((s) & 1) * BBUF;                                  \
        const __half* _bp = Bg + ((size_t)_n * Hh + j0) * KBE + _c * KS;                \
        _Pragma("unroll")                                                               \
        for (int i = 0; i < 4; i++) {                                                   \
            int idx = tid + i * 256, row = idx >> 3, seg = idx & 7;                     \
            CPA(_dst + row * ROWB + seg * 16, _bp + (size_t)row * KBE + seg * 8);       \
        }                                                                               \
        CPC();                                                                          \
    } while (0)

    // prologue: full A tile (8 chunk blocks) + B step 0 in one group
    {
#pragma unroll
        for (int i = 0; i < 16; i++) {
            int idx = tid + i * 256;
            int c = idx >> 9, row = (idx >> 3) & 63, seg = idx & 7;
            CPA(sb + c * (TM3 * ROWB) + row * ROWB + seg * 16,
                Ap + (size_t)row * KAE + c * KS + seg * 8);
        }
        int _n = 0, _c = 0;
        uint32_t _dst = sb + SM3_B;
        const __half* _bp = Bg + ((size_t)_n * Hh + j0) * KBE + _c * KS;
#pragma unroll
        for (int i = 0; i < 4; i++) {
            int idx = tid + i * 256, row = idx >> 3, seg = idx & 7;
            CPA(_dst + row * ROWB + seg * 16, _bp + (size_t)row * KBE + seg * 8);
        }
        CPC();
    }

    float acc[2][4][4];
#pragma unroll
    for (int a = 0; a < 2; a++)
#pragma unroll
        for (int b = 0; b < 4; b++)
#pragma unroll
            for (int c = 0; c < 4; c++) acc[a][b][c] = 0.0f;

    float* red = reinterpret_cast<float*>(smem + SM3_RED);

    for (int s = 0; s < 128; s++) {
        int n = s >> 3, c = s & 7;
        CPW0();                       // B(s) [+ A on s=0] arrived
        __syncthreads();              // all warps done with buffer (s+1)&1 from step s-1
        if (s + 1 < 128) LOAD_B(s + 1);
        uint32_t abase = sb + c * (TM3 * ROWB);
        uint32_t bbase = (uint32_t)(((s) & 1) * BBUF);
#pragma unroll
        for (int kk = 0; kk < 4; kk++) {
            uint32_t fa[2][4], fb[2][4];
#pragma unroll
            for (int p = 0; p < 2; p++) LDSM4(fb[p], sb + bbase + b_base[p] + kk * 32);
#pragma unroll
            for (int mi = 0; mi < 2; mi++) LDSM4(fa[mi], abase + a_base[mi] + kk * 32);
#pragma unroll
            for (int mi = 0; mi < 2; mi++)
#pragma unroll
                for (int p = 0; p < 2; p++) {
                    MMA(acc[mi][2 * p],     fa[mi], fb[p][0], fb[p][2]);
                    MMA(acc[mi][2 * p + 1], fa[mi], fb[p][1], fb[p][3]);
                }
        }
        if (c == 7) {
            // epilogue for this n
            float rs[2][2];
#pragma unroll
            for (int mi = 0; mi < 2; mi++)
#pragma unroll
                for (int half = 0; half < 2; half++) {
                    float sv = 0.0f;
#pragma unroll
                    for (int g = 0; g < 4; g++) {
                        int col = j0 + wn * 32 + g * 8 + (lane & 3) * 2;
                        int bi = n * Hh + col;
                        sv += lrelu(acc[mi][g][half * 2]     + __ldg(&bias[bi]))     * __ldg(&wc2[bi]);
                        sv += lrelu(acc[mi][g][half * 2 + 1] + __ldg(&bias[bi + 1])) * __ldg(&wc2[bi + 1]);
                    }
                    sv += __shfl_xor_sync(0xffffffffu, sv, 1);
                    sv += __shfl_xor_sync(0xffffffffu, sv, 2);
                    rs[mi][half] = sv;
                }
            __syncthreads();          // previous epilogue's red reads done
            if ((lane & 3) == 0) {
#pragma unroll
                for (int mi = 0; mi < 2; mi++)
#pragma unroll
                    for (int half = 0; half < 2; half++) {
                        int rl = wm * 32 + mi * 16 + (lane >> 2) + half * 8;
                        red[wn * 64 + rl] = rs[mi][half];
                    }
            }
            __syncthreads();
            if (tid < 64) {
                float tot = red[tid] + red[64 + tid] + red[128 + tid] + red[192 + tid];
                g_part[((size_t)jt * M_TOT + m0 + tid) * Nn + n] = tot;
            }
            // reset accumulators for next n
#pragma unroll
            for (int a = 0; a < 2; a++)
#pragma unroll
                for (int b = 0; b < 4; b++)
#pragma unroll
                    for (int e = 0; e < 4; e++) acc[a][b][e] = 0.0f;
        }
    }
#undef LOAD_B
}

// ---------------------------------------------------------------------------
// finalize: full_out = sum parts + bc2 ; sigmoid diagonal for out (fused)
// ---------------------------------------------------------------------------
__global__ void k_fin(const float* __restrict__ bc2, float* __restrict__ out) {
    int i = blockIdx.x * blockDim.x + threadIdx.x;
    if (i >= M_TOT * Nn) return;
    int nn = i & 15;
    out[16384 + i] = g_part[i] + g_part[262144 + i] + g_part[2 * 262144 + i]
                   + g_part[3 * 262144 + i] + bc2[nn];
    if (i < Bsz * Nn) {
        int b = i >> 4;
        size_t idx = ((size_t)nn * Bsz + b) * Nn + nn;
        float lg = g_part[idx] + g_part[262144 + idx] + g_part[2 * 262144 + idx]
                 + g_part[3 * 262144 + idx] + bc2[nn];
        out[i] = 1.0f / (1.0f + expf(-lg));
    }
}

// ---------------------------------------------------------------------------
extern "C" void kernel_launch(void* const* d_in, const int* in_sizes, int n_in,
                              void* d_out, int out_size) {
    const float* x   = (const float*)d_in[0];
    const float* Ws1 = (const float*)d_in[1];
    const float* bs1 = (const float*)d_in[2];
    const float* Ws2 = (const float*)d_in[3];
    const float* bs2 = (const float*)d_in[4];
    const float* Wc1 = (const float*)d_in[5];
    const float* bc1 = (const float*)d_in[6];
    const float* Wc2 = (const float*)d_in[7];
    const float* bc2 = (const float*)d_in[8];
    float* out = (float*)d_out;

    cudaFuncSetAttribute(k_g12, cudaFuncAttributeMaxDynamicSharedMemorySize, SMEM12);
    cudaFuncSetAttribute(k_g3,  cudaFuncAttributeMaxDynamicSharedMemorySize, SMEM3);

    __half *A0p, *A1p, *W1p, *W2p, *Wcp;
    cudaGetSymbolAddress((void**)&A0p, g_A0);
    cudaGetSymbolAddress((void**)&A1p, g_A1);
    cudaGetSymbolAddress((void**)&W1p, g_W1);
    cudaGetSymbolAddress((void**)&W2p, g_W2);
    cudaGetSymbolAddress((void**)&Wcp, g_Wc);

    k_convert_x<<<Bsz, 256>>>(x);
    k_convert_w<<<dim3(16, 16, 18), dim3(32, 8)>>>(Ws1, Ws2, Wc1);

    k_g12<<<dim3(4, 128), 256, SMEM12>>>(A0p, W1p, bs1, A1p);
    k_g12<<<dim3(4, 128), 256, SMEM12>>>(A1p, W2p, bs2, A0p);
    k_g3<<<dim3(4, 256), 256, SMEM3>>>(A0p, Wcp, bc1, Wc2);

    k_fin<<<(M_TOT * Nn + 255) / 256, 256>>>(bc2, out);
}

// round 10
// speedup vs baseline: 6.3254x; 1.0603x over previous
#include <cuda_runtime.h>
#include <cuda_fp16.h>
#include <cstdint>
#include <math.h>

#define Bsz 1024
#define Dd  512
#define Nn  16
#define Hh  512
#define M_TOT 16384
#define KAE  512                 // A row elems (hi-only fp16)
#define KBE  512                 // B row elems
#define KS   64                  // K elems per chunk
#define NCH  8
#define ROWB 144                 // smem row stride (128B data + 16B pad)

// ---- GEMM1/2: CTA 64x128, 3-stage ----
#define TM12    64
#define SB12    (TM12 * ROWB)        // 9216
#define STG12   (SB12 + 128 * ROWB)  // 27648
#define SMEM12  (3 * STG12)          // 82944

// ---- GEMM3: CTA 128x128, 3-stage (R8 streaming design) ----
#define TM3     128
#define STG3_A  (TM3 * ROWB)         // 18432
#define STG3    (2 * STG3_A)         // 36864
#define SMEM3   (3 * STG3)           // 110592

// ---------------- scratch ----------------
__device__ __half g_A0[(size_t)M_TOT * KAE];
__device__ __half g_A1[(size_t)M_TOT * KAE];
__device__ __half g_W1[(size_t)Dd * KBE];
__device__ __half g_W2[(size_t)Dd * KBE];
__device__ __half g_Wc[(size_t)Nn * Hh * KBE];
__device__ float  g_part[4 * (size_t)M_TOT * Nn];

// ---------------- helpers ----------------
static __device__ __forceinline__ uint32_t smem_u32(const void* p) {
    uint32_t a;
    asm("{ .reg .u64 t; cvta.to.shared.u64 t, %1; cvt.u32.u64 %0, t; }" : "=r"(a) : "l"(p));
    return a;
}
static __device__ __forceinline__ float lrelu(float v) { return v >= 0.0f ? v : 0.1f * v; }

#define LDSM4(r, a)                                                                     \
    asm volatile("ldmatrix.sync.aligned.m8n8.x4.shared.b16 {%0,%1,%2,%3}, [%4];"        \
                 : "=r"((r)[0]), "=r"((r)[1]), "=r"((r)[2]), "=r"((r)[3]) : "r"(a))
#define MMA(d, a, b0, b1)                                                               \
    asm volatile("mma.sync.aligned.m16n8k16.row.col.f32.f16.f16.f32 "                   \
                 "{%0,%1,%2,%3},{%4,%5,%6,%7},{%8,%9},{%0,%1,%2,%3};"                   \
                 : "+f"((d)[0]), "+f"((d)[1]), "+f"((d)[2]), "+f"((d)[3])               \
                 : "r"((a)[0]), "r"((a)[1]), "r"((a)[2]), "r"((a)[3]), "r"(b0), "r"(b1))
#define CPA(dst, src) asm volatile("cp.async.cg.shared.global [%0], [%1], 16;" :: "r"(dst), "l"(src))
#define CPC()  asm volatile("cp.async.commit_group;" ::: "memory")
#define CPW1() asm volatile("cp.async.wait_group 1;" ::: "memory")
#define CPW0() asm volatile("cp.async.wait_group 0;" ::: "memory")

// ---------------------------------------------------------------------------
// convert x (B, D, N) fp32 -> g_A0[m = n*B + b][d] fp16
// ---------------------------------------------------------------------------
__global__ void k_convert_x(const float* __restrict__ x) {
    __shared__ float sm[Dd * 17];
    int b = blockIdx.x;
    const float4* xp = reinterpret_cast<const float4*>(x + (size_t)b * Dd * Nn);
    for (int v = threadIdx.x; v < 2048; v += blockDim.x) {
        float4 q = xp[v];
        int d = v >> 2, n0 = (v & 3) * 4;
        sm[d * 17 + n0 + 0] = q.x; sm[d * 17 + n0 + 1] = q.y;
        sm[d * 17 + n0 + 2] = q.z; sm[d * 17 + n0 + 3] = q.w;
    }
    __syncthreads();
    int d0 = (threadIdx.x & 127) * 4;
    int nh = threadIdx.x >> 7;
    for (int nb = 0; nb < Nn; nb += 2) {
        int n = nb + nh;
        __half* row = g_A0 + (size_t)(n * Bsz + b) * KAE;
        __half h[4];
#pragma unroll
        for (int e = 0; e < 4; e++) h[e] = __float2half_rn(sm[(d0 + e) * 17 + n]);
        *reinterpret_cast<uint2*>(row + d0) = *reinterpret_cast<uint2*>(h);
    }
}

// ---------------------------------------------------------------------------
// convert weights W[k][j] -> B'[j][k] fp16 transposed
// ---------------------------------------------------------------------------
__global__ void k_convert_w(const float* __restrict__ Ws1,
                            const float* __restrict__ Ws2,
                            const float* __restrict__ Wc1) {
    __shared__ float sm[32][33];
    int z = blockIdx.z;
    const float* in;
    __half* out;
    if (z == 0)      { in = Ws1; out = g_W1; }
    else if (z == 1) { in = Ws2; out = g_W2; }
    else             { in = Wc1 + (size_t)(z - 2) * Dd * Hh;
                       out = g_Wc + (size_t)(z - 2) * Hh * KBE; }
    int k0 = blockIdx.x * 32, j0 = blockIdx.y * 32;
    int tx = threadIdx.x, ty = threadIdx.y;
#pragma unroll
    for (int i = 0; i < 4; i++) {
        int r = ty + i * 8;
        sm[r][tx] = in[(size_t)(k0 + r) * Dd + j0 + tx];
    }
    __syncthreads();
#pragma unroll
    for (int i = 0; i < 4; i++) {
        int r = ty + i * 8;
        out[(size_t)(j0 + r) * KBE + k0 + tx] = __float2half_rn(sm[tx][r]);
    }
}

// ---------------------------------------------------------------------------
// GEMM1/2: CTA 64x128, warp 32x32, hi-only. Aout = fp16(lrelu(acc + bias))
// ---------------------------------------------------------------------------
__global__ void __launch_bounds__(256, 2)
k_g12(const __half* __restrict__ Ag,
      const __half* __restrict__ Bg,
      const float* __restrict__ bias,
      __half* __restrict__ Aout) {
    extern __shared__ char smem[];
    uint32_t sb = smem_u32(smem);
    int tid = threadIdx.x, lane = tid & 31, wid = tid >> 5;
    int wm = wid & 1, wn = wid >> 1;

    int jt = blockIdx.x;
    int m0 = blockIdx.y * TM12;
    int j0 = jt * 128;

    const __half* Ap = Ag + (size_t)m0 * KAE;
    const __half* Bp = Bg + (size_t)j0 * KBE;

    float acc[2][4][4];
#pragma unroll
    for (int a = 0; a < 2; a++)
#pragma unroll
        for (int b = 0; b < 4; b++)
#pragma unroll
            for (int c = 0; c < 4; c++) acc[a][b][c] = 0.0f;

    uint32_t a_off[2], b_off[2];
#pragma unroll
    for (int mi = 0; mi < 2; mi++)
        a_off[mi] = (uint32_t)((wm * 32 + mi * 16 + (lane & 15)) * ROWB + (lane >> 4) * 16);
#pragma unroll
    for (int p = 0; p < 2; p++)
        b_off[p] = (uint32_t)(SB12 + (wn * 32 + p * 16 + (lane & 15)) * ROWB + (lane >> 4) * 16);

#define STAGE_LOAD12(base, c)                                                           \
    do {                                                                                \
        int ko = (c) * KS;                                                              \
        _Pragma("unroll")                                                               \
        for (int i = 0; i < 2; i++) {                                                   \
            int idx = tid + i * 256, row = idx >> 3, seg = idx & 7;                     \
            CPA((base) + row * ROWB + seg * 16, Ap + (size_t)row * KAE + ko + seg * 8); \
        }                                                                               \
        _Pragma("unroll")                                                               \
        for (int i = 0; i < 4; i++) {                                                   \
            int idx = tid + i * 256, row = idx >> 3, seg = idx & 7;                     \
            CPA((base) + SB12 + row * ROWB + seg * 16,                                  \
                Bp + (size_t)row * KBE + ko + seg * 8);                                 \
        }                                                                               \
        CPC();                                                                          \
    } while (0)

    STAGE_LOAD12(sb, 0);
    STAGE_LOAD12(sb + STG12, 1);

    int sbuf = 0, wbuf = 2;
    for (int c = 0; c < NCH; c++) {
        if (c == NCH - 1) { CPW0(); } else { CPW1(); }
        __syncthreads();
        if (c + 2 < NCH) STAGE_LOAD12(sb + wbuf * STG12, c + 2);
        uint32_t base = sb + sbuf * STG12;
#pragma unroll
        for (int kk = 0; kk < 4; kk++) {
            uint32_t fa[2][4], fb[2][4];
#pragma unroll
            for (int p = 0; p < 2; p++) LDSM4(fb[p], base + b_off[p] + kk * 32);
#pragma unroll
            for (int mi = 0; mi < 2; mi++) LDSM4(fa[mi], base + a_off[mi] + kk * 32);
#pragma unroll
            for (int mi = 0; mi < 2; mi++)
#pragma unroll
                for (int p = 0; p < 2; p++) {
                    MMA(acc[mi][2 * p],     fa[mi], fb[p][0], fb[p][2]);
                    MMA(acc[mi][2 * p + 1], fa[mi], fb[p][1], fb[p][3]);
                }
        }
        sbuf = (sbuf == 2) ? 0 : sbuf + 1;
        wbuf = (wbuf == 2) ? 0 : wbuf + 1;
    }
#undef STAGE_LOAD12

#pragma unroll
    for (int mi = 0; mi < 2; mi++)
#pragma unroll
        for (int half = 0; half < 2; half++) {
            int row = m0 + wm * 32 + mi * 16 + (lane >> 2) + half * 8;
            __half* rowp = Aout + (size_t)row * KAE;
#pragma unroll
            for (int g = 0; g < 4; g++) {
                int col = j0 + wn * 32 + g * 8 + (lane & 3) * 2;
                float v0 = lrelu(acc[mi][g][half * 2]     + __ldg(&bias[col]));
                float v1 = lrelu(acc[mi][g][half * 2 + 1] + __ldg(&bias[col + 1]));
                __half hh[2] = {__float2half_rn(v0), __float2half_rn(v1)};
                *reinterpret_cast<uint32_t*>(rowp + col) = *reinterpret_cast<uint32_t*>(hh);
            }
        }
}

// ---------------------------------------------------------------------------
// GEMM3 (R8 streaming design): CTA 128x128, warp 64x32, hi-only, K = 512.
// g_part[jt][m][n] = sum_h lrelu(acc + bc1[n,h]) * Wc2[n,h]
// ---------------------------------------------------------------------------
__global__ void __launch_bounds__(256, 2)
k_g3(const __half* __restrict__ Ag,
     const __half* __restrict__ Bg,
     const float* __restrict__ bias,
     const float* __restrict__ wc2) {
    extern __shared__ char smem[];
    uint32_t sb = smem_u32(smem);
    int tid = threadIdx.x, lane = tid & 31, wid = tid >> 5;
    int wm = wid & 1, wn = wid >> 1;

    int jt = blockIdx.x;
    int n  = blockIdx.y;
    int m0 = blockIdx.z * TM3;
    int j0 = jt * 128;

    const __half* Ap = Ag + (size_t)m0 * KAE;
    const __half* Bp = Bg + ((size_t)n * Hh + j0) * KBE;

    float acc[4][4][4];
#pragma unroll
    for (int a = 0; a < 4; a++)
#pragma unroll
        for (int b = 0; b < 4; b++)
#pragma unroll
            for (int c = 0; c < 4; c++) acc[a][b][c] = 0.0f;

    uint32_t a_off[4], b_off[2];
#pragma unroll
    for (int mi = 0; mi < 4; mi++)
        a_off[mi] = (uint32_t)((wm * 64 + mi * 16 + (lane & 15)) * ROWB + (lane >> 4) * 16);
#pragma unroll
    for (int p = 0; p < 2; p++)
        b_off[p] = (uint32_t)(STG3_A + (wn * 32 + p * 16 + (lane & 15)) * ROWB + (lane >> 4) * 16);

#define STAGE_LOAD3(base, c)                                                            \
    do {                                                                                \
        int ko = (c) * KS;                                                              \
        _Pragma("unroll")                                                               \
        for (int i = 0; i < 4; i++) {                                                   \
            int idx = tid + i * 256, row = idx >> 3, seg = idx & 7;                     \
            CPA((base) + row * ROWB + seg * 16, Ap + (size_t)row * KAE + ko + seg * 8); \
        }                                                                               \
        _Pragma("unroll")                                                               \
        for (int i = 0; i < 4; i++) {                                                   \
            int idx = tid + i * 256, row = idx >> 3, seg = idx & 7;                     \
            CPA((base) + STG3_A + row * ROWB + seg * 16,                                \
                Bp + (size_t)row * KBE + ko + seg * 8);                                 \
        }                                                                               \
        CPC();                                                                          \
    } while (0)

    STAGE_LOAD3(sb, 0);
    STAGE_LOAD3(sb + STG3, 1);

    int sbuf = 0, wbuf = 2;
    for (int c = 0; c < NCH; c++) {
        if (c == NCH - 1) { CPW0(); } else { CPW1(); }
        __syncthreads();
        if (c + 2 < NCH) STAGE_LOAD3(sb + wbuf * STG3, c + 2);
        uint32_t base = sb + sbuf * STG3;
#pragma unroll
        for (int kk = 0; kk < 4; kk++) {
            uint32_t fa[4][4], fb[2][4];
#pragma unroll
            for (int p = 0; p < 2; p++) LDSM4(fb[p], base + b_off[p] + kk * 32);
#pragma unroll
            for (int mi = 0; mi < 4; mi++) LDSM4(fa[mi], base + a_off[mi] + kk * 32);
#pragma unroll
            for (int mi = 0; mi < 4; mi++)
#pragma unroll
                for (int p = 0; p < 2; p++) {
                    MMA(acc[mi][2 * p],     fa[mi], fb[p][0], fb[p][2]);
                    MMA(acc[mi][2 * p + 1], fa[mi], fb[p][1], fb[p][3]);
                }
        }
        sbuf = (sbuf == 2) ? 0 : sbuf + 1;
        wbuf = (wbuf == 2) ? 0 : wbuf + 1;
    }
#undef STAGE_LOAD3

    float rs[4][2];
#pragma unroll
    for (int mi = 0; mi < 4; mi++)
#pragma unroll
        for (int half = 0; half < 2; half++) {
            float s = 0.0f;
#pragma unroll
            for (int g = 0; g < 4; g++) {
                int col = j0 + wn * 32 + g * 8 + (lane & 3) * 2;
                int bi = n * Hh + col;
                s += lrelu(acc[mi][g][half * 2]     + __ldg(&bias[bi]))     * __ldg(&wc2[bi]);
                s += lrelu(acc[mi][g][half * 2 + 1] + __ldg(&bias[bi + 1])) * __ldg(&wc2[bi + 1]);
            }
            s += __shfl_xor_sync(0xffffffffu, s, 1);
            s += __shfl_xor_sync(0xffffffffu, s, 2);
            rs[mi][half] = s;
        }
    __syncthreads();
    float* red = reinterpret_cast<float*>(smem);
    if ((lane & 3) == 0) {
#pragma unroll
        for (int mi = 0; mi < 4; mi++)
#pragma unroll
            for (int half = 0; half < 2; half++) {
                int rl = wm * 64 + mi * 16 + (lane >> 2) + half * 8;
                red[wn * 128 + rl] = rs[mi][half];
            }
    }
    __syncthreads();
    if (tid < 128) {
        float tot = red[tid] + red[128 + tid] + red[256 + tid] + red[384 + tid];
        g_part[((size_t)jt * M_TOT + m0 + tid) * Nn + n] = tot;
    }
}

// ---------------------------------------------------------------------------
// finalize: full_out = sum parts + bc2 ; sigmoid diagonal for out (fused)
// ---------------------------------------------------------------------------
__global__ void k_fin(const float* __restrict__ bc2, float* __restrict__ out) {
    int i = blockIdx.x * blockDim.x + threadIdx.x;
    if (i >= M_TOT * Nn) return;
    int nn = i & 15;
    out[16384 + i] = g_part[i] + g_part[262144 + i] + g_part[2 * 262144 + i]
                   + g_part[3 * 262144 + i] + bc2[nn];
    if (i < Bsz * Nn) {
        int b = i >> 4;
        size_t idx = ((size_t)nn * Bsz + b) * Nn + nn;
        float lg = g_part[idx] + g_part[262144 + idx] + g_part[2 * 262144 + idx]
                 + g_part[3 * 262144 + idx] + bc2[nn];
        out[i] = 1.0f / (1.0f + expf(-lg));
    }
}

// ---------------------------------------------------------------------------
extern "C" void kernel_launch(void* const* d_in, const int* in_sizes, int n_in,
                              void* d_out, int out_size) {
    const float* x   = (const float*)d_in[0];
    const float* Ws1 = (const float*)d_in[1];
    const float* bs1 = (const float*)d_in[2];
    const float* Ws2 = (const float*)d_in[3];
    const float* bs2 = (const float*)d_in[4];
    const float* Wc1 = (const float*)d_in[5];
    const float* bc1 = (const float*)d_in[6];
    const float* Wc2 = (const float*)d_in[7];
    const float* bc2 = (const float*)d_in[8];
    float* out = (float*)d_out;

    cudaFuncSetAttribute(k_g12, cudaFuncAttributeMaxDynamicSharedMemorySize, SMEM12);
    cudaFuncSetAttribute(k_g3,  cudaFuncAttributeMaxDynamicSharedMemorySize, SMEM3);

    __half *A0p, *A1p, *W1p, *W2p, *Wcp;
    cudaGetSymbolAddress((void**)&A0p, g_A0);
    cudaGetSymbolAddress((void**)&A1p, g_A1);
    cudaGetSymbolAddress((void**)&W1p, g_W1);
    cudaGetSymbolAddress((void**)&W2p, g_W2);
    cudaGetSymbolAddress((void**)&Wcp, g_Wc);

    k_convert_x<<<Bsz, 256>>>(x);
    k_convert_w<<<dim3(16, 16, 18), dim3(32, 8)>>>(Ws1, Ws2, Wc1);

    k_g12<<<dim3(4, 256), 256, SMEM12>>>(A0p, W1p, bs1, A1p);
    k_g12<<<dim3(4, 256), 256, SMEM12>>>(A1p, W2p, bs2, A0p);
    k_g3<<<dim3(4, 16, 128), 256, SMEM3>>>(A0p, Wcp, bc1, Wc2);

    k_fin<<<(M_TOT * Nn + 255) / 256, 256>>>(bc2, out);
}